// round 5
// baseline (speedup 1.0000x reference)
#include <cuda_runtime.h>
#include <cuda_bf16.h>
#include <cuda_fp16.h>
#include <math.h>
#include <stdint.h>

#define SEQ    2048
#define BATCH  2
#define MTOK   4096      // BATCH*SEQ
#define DM     1024
#define NH     16
#define DHEAD  64
#define NEGV   -1000000000.0f

// -------- scratch (device globals; no allocation allowed) --------
__device__ float g_xln[MTOK * DM];
__device__ float g_qb [MTOK * DM];
__device__ float g_kb [MTOK * DM];
__device__ float g_vb [MTOK * DM];
__device__ float g_ab [MTOK * DM];
__device__ float g_hb [MTOK * DM];
__device__ float g_rb [MTOK * DM];
__device__ float g_zb [MTOK * DM];
__device__ float g_tb [MTOK * 4 * DM];
__device__ float g_wt [16 * 1024 * 1024];   // transposed weights [N][K]

#define WT_Q1   (0u)
#define WT_K1   (1u << 20)
#define WT_V1   (2u << 20)
#define WT_O1   (3u << 20)
#define WT_Q2   (4u << 20)
#define WT_K2   (5u << 20)
#define WT_V2   (6u << 20)
#define WT_O2   (7u << 20)
#define WT_M1   (8u << 20)   // [4096][1024]
#define WT_M2   (12u << 20)  // [1024][4096]

// ============================================================
// helpers
// ============================================================
__device__ __forceinline__ uint32_t smem_u32(const void* p) {
    uint32_t a;
    asm("{ .reg .u64 t; cvta.to.shared.u64 t, %1; cvt.u32.u64 %0, t; }"
        : "=r"(a) : "l"(p));
    return a;
}

#define LDSM_X4(r0, r1, r2, r3, addr) \
    asm volatile("ldmatrix.sync.aligned.m8n8.x4.shared.b16 {%0,%1,%2,%3}, [%4];" \
                 : "=r"(r0), "=r"(r1), "=r"(r2), "=r"(r3) : "r"(addr))

#define MMA_BF16(c, a, b0, b1) \
    asm volatile("mma.sync.aligned.m16n8k16.row.col.f32.bf16.bf16.f32 " \
                 "{%0,%1,%2,%3}, {%4,%5,%6,%7}, {%8,%9}, {%0,%1,%2,%3};" \
                 : "+f"((c)[0]), "+f"((c)[1]), "+f"((c)[2]), "+f"((c)[3]) \
                 : "r"((a)[0]), "r"((a)[1]), "r"((a)[2]), "r"((a)[3]), \
                   "r"(b0), "r"(b1))

#define MMA_F16(c, a, b0, b1) \
    asm volatile("mma.sync.aligned.m16n8k16.row.col.f32.f16.f16.f32 " \
                 "{%0,%1,%2,%3}, {%4,%5,%6,%7}, {%8,%9}, {%0,%1,%2,%3};" \
                 : "+f"((c)[0]), "+f"((c)[1]), "+f"((c)[2]), "+f"((c)[3]) \
                 : "r"((a)[0]), "r"((a)[1]), "r"((a)[2]), "r"((a)[3]), \
                   "r"(b0), "r"(b1))

__device__ __forceinline__ uint32_t pack_h2(float a, float b) {
    __half2 h;
    h.x = __float2half(a); h.y = __float2half(b);
    return *(uint32_t*)&h;
}

__device__ __forceinline__ float block_sum(float v, float* red) {
    int lane = threadIdx.x & 31, w = threadIdx.x >> 5;
    #pragma unroll
    for (int o = 16; o > 0; o >>= 1) v += __shfl_xor_sync(0xffffffffu, v, o);
    __syncthreads();
    if (lane == 0) red[w] = v;
    __syncthreads();
    if (w == 0) {
        float x = (lane < 8) ? red[lane] : 0.0f;
        #pragma unroll
        for (int o = 4; o > 0; o >>= 1) x += __shfl_xor_sync(0xffffffffu, x, o);
        if (lane == 0) red[0] = x;
    }
    __syncthreads();
    return red[0];
}
__device__ __forceinline__ float gelu_exact(float x) {
    return 0.5f * x * (1.0f + erff(x * 0.7071067811865475f));
}

// -------- weight transpose: WT[n*K+k] = W[k*N+n] --------
__global__ __launch_bounds__(256) void transpose_kernel(
    const float* __restrict__ W, float* __restrict__ WT, int K, int N)
{
    __shared__ float t[32][33];
    int n0 = blockIdx.x * 32, k0 = blockIdx.y * 32;
    int tx = threadIdx.x & 31, ty = threadIdx.x >> 5;
    #pragma unroll
    for (int i = 0; i < 4; i++)
        t[ty + 8 * i][tx] = W[(size_t)(k0 + ty + 8 * i) * N + n0 + tx];
    __syncthreads();
    #pragma unroll
    for (int i = 0; i < 4; i++)
        WT[(size_t)(n0 + ty + 8 * i) * K + k0 + tx] = t[tx][ty + 8 * i];
}

// -------- fused embedding + LN1 --------
__global__ __launch_bounds__(256) void embed_ln_kernel(
    const int* __restrict__ ids, const float* __restrict__ tok,
    const float* __restrict__ pos, const float* __restrict__ gw,
    const float* __restrict__ bw, float* __restrict__ out)
{
    __shared__ float red[32];
    int row = blockIdx.x;
    int s   = row & (SEQ - 1);
    int id  = ids[row];
    int d   = threadIdx.x * 4;
    float4 t4 = *(const float4*)(tok + (size_t)id * DM + d);
    float4 p4 = *(const float4*)(pos + (size_t)s  * DM + d);
    float4 v;
    v.x = t4.x + p4.x; v.y = t4.y + p4.y; v.z = t4.z + p4.z; v.w = t4.w + p4.w;
    float mu = block_sum(v.x + v.y + v.z + v.w, red) * (1.0f / DM);
    float dx = v.x - mu, dy = v.y - mu, dz = v.z - mu, dw = v.w - mu;
    float var = block_sum(dx*dx + dy*dy + dz*dz + dw*dw, red) * (1.0f / DM);
    float rstd = rsqrtf(var + 1e-5f);
    float4 o;
    o.x = dx * rstd * gw[d+0] + bw[d+0];
    o.y = dy * rstd * gw[d+1] + bw[d+1];
    o.z = dz * rstd * gw[d+2] + bw[d+2];
    o.w = dw * rstd * gw[d+3] + bw[d+3];
    *(float4*)(out + (size_t)row * DM + d) = o;
}

// -------- plain LN --------
__global__ __launch_bounds__(256) void ln_kernel(
    const float* __restrict__ in, const float* __restrict__ gw,
    const float* __restrict__ bw, float* __restrict__ out)
{
    __shared__ float red[32];
    int row = blockIdx.x;
    int d   = threadIdx.x * 4;
    float4 v = *(const float4*)(in + (size_t)row * DM + d);
    float mu = block_sum(v.x + v.y + v.z + v.w, red) * (1.0f / DM);
    float dx = v.x - mu, dy = v.y - mu, dz = v.z - mu, dw = v.w - mu;
    float var = block_sum(dx*dx + dy*dy + dz*dz + dw*dw, red) * (1.0f / DM);
    float rstd = rsqrtf(var + 1e-5f);
    float4 o;
    o.x = dx * rstd * gw[d+0] + bw[d+0];
    o.y = dy * rstd * gw[d+1] + bw[d+1];
    o.z = dz * rstd * gw[d+2] + bw[d+2];
    o.w = dw * rstd * gw[d+3] + bw[d+3];
    *(float4*)(out + (size_t)row * DM + d) = o;
}

// ============================================================
// bf16x3-split tensor-core GEMM (mma.sync m16n8k16) — unchanged from R4
// ============================================================
#define GTILE 10240
#define GEMM_SMEM (2 * 4 * GTILE)   // 81920

__global__ __launch_bounds__(256) void gemm_bf16_kernel(
    const float* __restrict__ A, const float* __restrict__ WT,
    const float* __restrict__ bias, const float* __restrict__ R,
    float* __restrict__ C, int M, int N, int K, int epi)
{
    extern __shared__ char smem[];
    const int tid = threadIdx.x, wid = tid >> 5, lane = tid & 31;
    const int m0 = blockIdx.y * 128, n0 = blockIdx.x * 128;
    const int warpM = (wid & 3) * 32, warpN = (wid >> 2) * 64;

    float acc[2][8][4];
    #pragma unroll
    for (int i = 0; i < 2; i++)
        #pragma unroll
        for (int j = 0; j < 8; j++)
            #pragma unroll
            for (int q = 0; q < 4; q++) acc[i][j][q] = 0.0f;

    const int srow = tid >> 1, skh = (tid & 1) * 16;
    const float* Ag = A  + (size_t)(m0 + srow) * K + skh;
    const float* Bg = WT + (size_t)(n0 + srow) * K + skh;

    const uint32_t sb = smem_u32(smem);
    const int a_stat = (warpM + ((lane >> 3) & 1) * 8 + (lane & 7)) * 40 + (lane >> 4) * 8;
    const int b_stat = (warpN + ((lane >> 4) & 1) * 8 + (lane & 7)) * 40 + ((lane >> 3) & 1) * 8;
    const int s_off  = (srow * 40 + skh) * 2;

    float4 ra[4], rb[4];
    const int NKB = K >> 5;

#define LOAD_REGS(kb) { \
    _Pragma("unroll") for (int i = 0; i < 4; i++) { \
        ra[i] = *(const float4*)(Ag + (kb) * 32 + i * 4); \
        rb[i] = *(const float4*)(Bg + (kb) * 32 + i * 4); } }

#define STORE_SMEM(buf) { \
    char* base = smem + (buf) * 4 * GTILE; \
    _Pragma("unroll") for (int i = 0; i < 4; i++) { \
        float av[4] = {ra[i].x, ra[i].y, ra[i].z, ra[i].w}; \
        float bv[4] = {rb[i].x, rb[i].y, rb[i].z, rb[i].w}; \
        _Pragma("unroll") for (int j = 0; j < 2; j++) { \
            int off = s_off + (i * 4 + 2 * j) * 2; \
            float x0 = av[2*j], x1 = av[2*j+1]; \
            __nv_bfloat162 h2 = __floats2bfloat162_rn(x0, x1); \
            __nv_bfloat162 l2 = __floats2bfloat162_rn( \
                x0 - __bfloat162float(h2.x), x1 - __bfloat162float(h2.y)); \
            *(uint32_t*)(base + off)             = *(uint32_t*)&h2; \
            *(uint32_t*)(base + GTILE + off)     = *(uint32_t*)&l2; \
            x0 = bv[2*j]; x1 = bv[2*j+1]; \
            h2 = __floats2bfloat162_rn(x0, x1); \
            l2 = __floats2bfloat162_rn( \
                x0 - __bfloat162float(h2.x), x1 - __bfloat162float(h2.y)); \
            *(uint32_t*)(base + 2 * GTILE + off) = *(uint32_t*)&h2; \
            *(uint32_t*)(base + 3 * GTILE + off) = *(uint32_t*)&l2; \
        } } }

#define COMPUTE(buf) { \
    uint32_t tb0 = sb + (buf) * 4 * GTILE; \
    _Pragma("unroll") for (int ks = 0; ks < 2; ks++) { \
        const int Cc = ks * 16; \
        uint32_t fa[2][4], fl[2][4], bh[4][4], bl[4][4]; \
        _Pragma("unroll") for (int mb = 0; mb < 2; mb++) { \
            uint32_t ad = tb0 + (uint32_t)(a_stat + mb * 640 + Cc) * 2; \
            LDSM_X4(fa[mb][0], fa[mb][1], fa[mb][2], fa[mb][3], ad); \
            LDSM_X4(fl[mb][0], fl[mb][1], fl[mb][2], fl[mb][3], ad + GTILE); \
        } \
        _Pragma("unroll") for (int p = 0; p < 4; p++) { \
            uint32_t bd = tb0 + 2 * GTILE + (uint32_t)(b_stat + p * 640 + Cc) * 2; \
            LDSM_X4(bh[p][0], bh[p][1], bh[p][2], bh[p][3], bd); \
            LDSM_X4(bl[p][0], bl[p][1], bl[p][2], bl[p][3], bd + GTILE); \
        } \
        _Pragma("unroll") for (int mb = 0; mb < 2; mb++) \
        _Pragma("unroll") for (int nb = 0; nb < 8; nb++) { \
            const int p = nb >> 1, q = (nb & 1) * 2; \
            MMA_BF16(acc[mb][nb], fa[mb], bh[p][q], bh[p][q + 1]); \
            MMA_BF16(acc[mb][nb], fa[mb], bl[p][q], bl[p][q + 1]); \
            MMA_BF16(acc[mb][nb], fl[mb], bh[p][q], bh[p][q + 1]); \
        } } }

    LOAD_REGS(0);
    STORE_SMEM(0);
    __syncthreads();

    for (int kb = 0; kb < NKB; kb++) {
        if (kb + 1 < NKB) LOAD_REGS(kb + 1);
        COMPUTE(kb & 1);
        if (kb + 1 < NKB) {
            __syncthreads();
            STORE_SMEM((kb + 1) & 1);
            __syncthreads();
        }
    }

    const int g = lane >> 2, t = lane & 3;
    #pragma unroll
    for (int mb = 0; mb < 2; mb++)
        #pragma unroll
        for (int nb = 0; nb < 8; nb++) {
            int row = m0 + warpM + mb * 16 + g;
            int col = n0 + warpN + nb * 8 + 2 * t;
            float2 b2 = *(const float2*)(bias + col);
            float v0 = acc[mb][nb][0] + b2.x, v1 = acc[mb][nb][1] + b2.y;
            float v2 = acc[mb][nb][2] + b2.x, v3 = acc[mb][nb][3] + b2.y;
            if (epi == 1) {
                v0 = gelu_exact(v0); v1 = gelu_exact(v1);
                v2 = gelu_exact(v2); v3 = gelu_exact(v3);
            } else if (epi == 2) {
                float2 r0 = *(const float2*)(R + (size_t)row * N + col);
                float2 r1 = *(const float2*)(R + (size_t)(row + 8) * N + col);
                v0 += r0.x; v1 += r0.y; v2 += r1.x; v3 += r1.y;
            }
            float2 o0 = {v0, v1}, o1 = {v2, v3};
            *(float2*)(C + (size_t)row * N + col) = o0;
            *(float2*)(C + (size_t)(row + 8) * N + col) = o1;
        }
}

// ============================================================
// flash attention, mma.sync fp16 (QK fp16x3 split; P,V fp16)
// 128 threads / 4 warps; BQ=64 (16 rows/warp); BK=64
// smem: Khi[64][72] | Klo[64][72] | Vt[64][72] | nadd[64]
// (K region doubles as Q hi/lo staging before the main loop)
// ============================================================
#define FS   72                        // half-element stride per row
#define FOFF_KLO 9216
#define FOFF_VT  18432
#define FOFF_NAD 27648
#define FLASH_SMEM (27648 + 256)

__global__ __launch_bounds__(128) void flash_mma_kernel(
    const float* __restrict__ Qg, const float* __restrict__ Kg,
    const float* __restrict__ Vg, const int* __restrict__ ids,
    float* __restrict__ Og, int causal)
{
    extern __shared__ char fsm[];
    const uint32_t sb = smem_u32(fsm);
    float* nadd = (float*)(fsm + FOFF_NAD);

    const int tid = threadIdx.x, wid = tid >> 5, lane = tid & 31;
    const int qt = blockIdx.x, h = blockIdx.y, b = blockIdx.z;
    const int qbase = qt * 64;
    const int g = lane >> 2, t = lane & 3;

    const float* Qp = Qg + (size_t)b * SEQ * DM + h * DHEAD;
    const float* Kp = Kg + (size_t)b * SEQ * DM + h * DHEAD;
    const float* Vp = Vg + (size_t)b * SEQ * DM + h * DHEAD;

    // ---- stage Q (hi at 0, lo at FOFF_KLO) ----
    {
        int r = tid >> 1, c0 = (tid & 1) * 32;
        const float* gp = Qp + (size_t)(qbase + r) * DM + c0;
        #pragma unroll
        for (int u = 0; u < 8; u++) {
            float4 q4 = *(const float4*)(gp + u * 4);
            float xv[4] = {q4.x, q4.y, q4.z, q4.w};
            #pragma unroll
            for (int e = 0; e < 2; e++) {
                float x0 = xv[2*e], x1 = xv[2*e+1];
                __half h0 = __float2half(x0), h1 = __float2half(x1);
                float l0 = x0 - __half2float(h0), l1 = x1 - __half2float(h1);
                int off = (r * FS + c0 + u * 4 + 2 * e) * 2;
                *(uint32_t*)(fsm + off) = pack_h2(__half2float(h0), __half2float(h1));
                *(uint32_t*)(fsm + FOFF_KLO + off) = pack_h2(l0, l1);
            }
        }
    }
    __syncthreads();

    // ---- Q fragments to registers ----
    uint32_t qh[4][4], ql[4][4];
    {
        int arow = (lane & 15) + 16 * wid;
        int acb  = ((lane >> 4) & 1) * 8;
        #pragma unroll
        for (int kk = 0; kk < 4; kk++) {
            uint32_t ad = sb + (uint32_t)(arow * FS + acb + kk * 16) * 2;
            LDSM_X4(qh[kk][0], qh[kk][1], qh[kk][2], qh[kk][3], ad);
            LDSM_X4(ql[kk][0], ql[kk][1], ql[kk][2], ql[kk][3], ad + FOFF_KLO);
        }
    }

    float mA = -3.0e38f, mB = -3.0e38f, lA = 0.0f, lB = 0.0f;
    float O[8][4];
    #pragma unroll
    for (int nb = 0; nb < 8; nb++)
        #pragma unroll
        for (int q = 0; q < 4; q++) O[nb][q] = 0.0f;

    const int rowA = qbase + 16 * wid + g;

    const int nkt = causal ? (qt + 1) : (SEQ / 64);
    for (int kt = 0; kt < nkt; kt++) {
        const int kbase = kt * 64;
        const bool diag = causal && (kt == qt);
        __syncthreads();   // previous-tile reads done before overwrite

        // load K tile (split hi/lo)
        {
            int r = tid >> 1, c0 = (tid & 1) * 32;
            const float* gp = Kp + (size_t)(kbase + r) * DM + c0;
            #pragma unroll
            for (int u = 0; u < 8; u++) {
                float4 k4 = *(const float4*)(gp + u * 4);
                float xv[4] = {k4.x, k4.y, k4.z, k4.w};
                #pragma unroll
                for (int e = 0; e < 2; e++) {
                    float x0 = xv[2*e], x1 = xv[2*e+1];
                    __half h0 = __float2half(x0), h1 = __float2half(x1);
                    float l0 = x0 - __half2float(h0), l1 = x1 - __half2float(h1);
                    int off = (r * FS + c0 + u * 4 + 2 * e) * 2;
                    *(uint32_t*)(fsm + off) = pack_h2(__half2float(h0), __half2float(h1));
                    *(uint32_t*)(fsm + FOFF_KLO + off) = pack_h2(l0, l1);
                }
            }
            if (tid < 64)
                nadd[tid] = (ids[b * SEQ + kbase + tid] == 0) ? NEGV : 0.0f;
        }
        // load V transposed: Vt[d][key] fp16 (pair-packed keys)
        {
            int p = tid & 31, c0 = (tid >> 5) * 16;
            const float* v0 = Vp + (size_t)(kbase + 2 * p) * DM + c0;
            const float* v1 = v0 + DM;
            #pragma unroll
            for (int u = 0; u < 4; u++) {
                float4 a4 = *(const float4*)(v0 + u * 4);
                float4 b4 = *(const float4*)(v1 + u * 4);
                float av[4] = {a4.x, a4.y, a4.z, a4.w};
                float bv[4] = {b4.x, b4.y, b4.z, b4.w};
                #pragma unroll
                for (int e = 0; e < 4; e++) {
                    int col = c0 + u * 4 + e;
                    *(uint32_t*)(fsm + FOFF_VT + (col * FS + 2 * p) * 2) =
                        pack_h2(av[e], bv[e]);
                }
            }
        }
        __syncthreads();

        // ---- scores: S = Q K^T (fp16x3) ----
        float sc[8][4];
        #pragma unroll
        for (int nb = 0; nb < 8; nb++)
            #pragma unroll
            for (int q = 0; q < 4; q++) sc[nb][q] = 0.0f;

        #pragma unroll
        for (int kk = 0; kk < 4; kk++) {
            #pragma unroll
            for (int p = 0; p < 4; p++) {
                int brow = p * 16 + ((lane >> 4) & 1) * 8 + (lane & 7);
                int bcol = kk * 16 + ((lane >> 3) & 1) * 8;
                uint32_t bd = sb + (uint32_t)(brow * FS + bcol) * 2;
                uint32_t bh[4], bl[4];
                LDSM_X4(bh[0], bh[1], bh[2], bh[3], bd);
                LDSM_X4(bl[0], bl[1], bl[2], bl[3], bd + FOFF_KLO);
                MMA_F16(sc[2*p],   qh[kk], bh[0], bh[1]);
                MMA_F16(sc[2*p],   qh[kk], bl[0], bl[1]);
                MMA_F16(sc[2*p],   ql[kk], bh[0], bh[1]);
                MMA_F16(sc[2*p+1], qh[kk], bh[2], bh[3]);
                MMA_F16(sc[2*p+1], qh[kk], bl[2], bl[3]);
                MMA_F16(sc[2*p+1], ql[kk], bh[2], bh[3]);
            }
        }

        // ---- scale + masks ----
        float rmaxA = -3.0e38f, rmaxB = -3.0e38f;
        #pragma unroll
        for (int nb = 0; nb < 8; nb++) {
            int col0 = kbase + nb * 8 + 2 * t;
            float p0 = nadd[nb * 8 + 2 * t], p1 = nadd[nb * 8 + 2 * t + 1];
            float v0 = sc[nb][0] * 0.125f + p0;
            float v1 = sc[nb][1] * 0.125f + p1;
            float v2 = sc[nb][2] * 0.125f + p0;
            float v3 = sc[nb][3] * 0.125f + p1;
            if (diag) {
                if (col0     > rowA)     v0 += NEGV;
                if (col0 + 1 > rowA)     v1 += NEGV;
                if (col0     > rowA + 8) v2 += NEGV;
                if (col0 + 1 > rowA + 8) v3 += NEGV;
            }
            sc[nb][0] = v0; sc[nb][1] = v1; sc[nb][2] = v2; sc[nb][3] = v3;
            rmaxA = fmaxf(rmaxA, fmaxf(v0, v1));
            rmaxB = fmaxf(rmaxB, fmaxf(v2, v3));
        }
        #pragma unroll
        for (int o = 1; o <= 2; o <<= 1) {
            rmaxA = fmaxf(rmaxA, __shfl_xor_sync(0xffffffffu, rmaxA, o));
            rmaxB = fmaxf(rmaxB, __shfl_xor_sync(0xffffffffu, rmaxB, o));
        }
        float mnA = fmaxf(mA, rmaxA), mnB = fmaxf(mB, rmaxB);
        float aA = __expf(mA - mnA), aB = __expf(mB - mnB);
        mA = mnA; mB = mnB;

        // ---- exp, fp16 round, build PV A-frags ----
        uint32_t af[4][4];
        float sA = 0.0f, sB = 0.0f;
        #pragma unroll
        for (int nb = 0; nb < 8; nb++) {
            float p0 = __expf(sc[nb][0] - mnA);
            float p1 = __expf(sc[nb][1] - mnA);
            float p2 = __expf(sc[nb][2] - mnB);
            float p3 = __expf(sc[nb][3] - mnB);
            __half h0 = __float2half(p0), h1 = __float2half(p1);
            __half h2 = __float2half(p2), h3 = __float2half(p3);
            sA += __half2float(h0) + __half2float(h1);
            sB += __half2float(h2) + __half2float(h3);
            __half2 u01; u01.x = h0; u01.y = h1;
            __half2 u23; u23.x = h2; u23.y = h3;
            int kk = nb >> 1, hi = nb & 1;
            af[kk][hi * 2 + 0] = *(uint32_t*)&u01;
            af[kk][hi * 2 + 1] = *(uint32_t*)&u23;
        }
        #pragma unroll
        for (int o = 1; o <= 2; o <<= 1) {
            sA += __shfl_xor_sync(0xffffffffu, sA, o);
            sB += __shfl_xor_sync(0xffffffffu, sB, o);
        }
        lA = lA * aA + sA; lB = lB * aB + sB;
        #pragma unroll
        for (int nb = 0; nb < 8; nb++) {
            O[nb][0] *= aA; O[nb][1] *= aA;
            O[nb][2] *= aB; O[nb][3] *= aB;
        }

        // ---- O += P V ----
        #pragma unroll
        for (int kk = 0; kk < 4; kk++) {
            #pragma unroll
            for (int p = 0; p < 4; p++) {
                int brow = p * 16 + ((lane >> 4) & 1) * 8 + (lane & 7);
                int bcol = kk * 16 + ((lane >> 3) & 1) * 8;
                uint32_t bd = sb + FOFF_VT + (uint32_t)(brow * FS + bcol) * 2;
                uint32_t bv[4];
                LDSM_X4(bv[0], bv[1], bv[2], bv[3], bd);
                MMA_F16(O[2*p],   af[kk], bv[0], bv[1]);
                MMA_F16(O[2*p+1], af[kk], bv[2], bv[3]);
            }
        }
    }

    // ---- write out ----
    float iA = 1.0f / lA, iB = 1.0f / lB;
    #pragma unroll
    for (int nb = 0; nb < 8; nb++) {
        int col = h * DHEAD + nb * 8 + 2 * t;
        size_t off0 = ((size_t)b * SEQ + rowA) * DM + col;
        size_t off1 = ((size_t)b * SEQ + rowA + 8) * DM + col;
        float2 o0 = {O[nb][0] * iA, O[nb][1] * iA};
        float2 o1 = {O[nb][2] * iB, O[nb][3] * iB};
        *(float2*)(Og + off0) = o0;
        *(float2*)(Og + off1) = o1;
    }
}

// ============================================================
// host pipeline
// ============================================================
extern "C" void kernel_launch(void* const* d_in, const int* in_sizes, int n_in,
                              void* d_out, int out_size)
{
    const float* input_embedding = (const float*)d_in[0];
    const int*   input_ids       = (const int*)  d_in[1];
    const int*   target_ids      = (const int*)  d_in[2];
    const float* tok_emb = (const float*)d_in[3];
    const float* pos_emb = (const float*)d_in[4];
    const float* ln1_g = (const float*)d_in[5],  *ln1_b = (const float*)d_in[6];
    const float* q1_w  = (const float*)d_in[7],  *q1_b  = (const float*)d_in[8];
    const float* k1_w  = (const float*)d_in[9],  *k1_b  = (const float*)d_in[10];
    const float* v1_w  = (const float*)d_in[11], *v1_b  = (const float*)d_in[12];
    const float* out1_w= (const float*)d_in[13], *out1_b= (const float*)d_in[14];
    const float* ln2_g = (const float*)d_in[15], *ln2_b = (const float*)d_in[16];
    const float* q2_w  = (const float*)d_in[17], *q2_b  = (const float*)d_in[18];
    const float* k2_w  = (const float*)d_in[19], *k2_b  = (const float*)d_in[20];
    const float* v2_w  = (const float*)d_in[21], *v2_b  = (const float*)d_in[22];
    const float* out2_w= (const float*)d_in[23], *out2_b= (const float*)d_in[24];
    const float* ln3_g = (const float*)d_in[25], *ln3_b = (const float*)d_in[26];
    const float* mlp_w1= (const float*)d_in[27], *mlp_b1= (const float*)d_in[28];
    const float* mlp_w2= (const float*)d_in[29], *mlp_b2= (const float*)d_in[30];

    float *xln, *qb, *kb, *vb, *ab, *hb, *rb, *zb, *tb, *wt;
    cudaGetSymbolAddress((void**)&xln, g_xln);
    cudaGetSymbolAddress((void**)&qb,  g_qb);
    cudaGetSymbolAddress((void**)&kb,  g_kb);
    cudaGetSymbolAddress((void**)&vb,  g_vb);
    cudaGetSymbolAddress((void**)&ab,  g_ab);
    cudaGetSymbolAddress((void**)&hb,  g_hb);
    cudaGetSymbolAddress((void**)&rb,  g_rb);
    cudaGetSymbolAddress((void**)&zb,  g_zb);
    cudaGetSymbolAddress((void**)&tb,  g_tb);
    cudaGetSymbolAddress((void**)&wt,  g_wt);

    cudaFuncSetAttribute(gemm_bf16_kernel,
                         cudaFuncAttributeMaxDynamicSharedMemorySize, GEMM_SMEM);

    // ---- transpose all weights into [N][K] scratch ----
    {
        dim3 g1(DM / 32, DM / 32);
        transpose_kernel<<<g1, 256>>>(q1_w,  wt + WT_Q1, DM, DM);
        transpose_kernel<<<g1, 256>>>(k1_w,  wt + WT_K1, DM, DM);
        transpose_kernel<<<g1, 256>>>(v1_w,  wt + WT_V1, DM, DM);
        transpose_kernel<<<g1, 256>>>(out1_w,wt + WT_O1, DM, DM);
        transpose_kernel<<<g1, 256>>>(q2_w,  wt + WT_Q2, DM, DM);
        transpose_kernel<<<g1, 256>>>(k2_w,  wt + WT_K2, DM, DM);
        transpose_kernel<<<g1, 256>>>(v2_w,  wt + WT_V2, DM, DM);
        transpose_kernel<<<g1, 256>>>(out2_w,wt + WT_O2, DM, DM);
        dim3 gm1(4 * DM / 32, DM / 32);
        transpose_kernel<<<gm1, 256>>>(mlp_w1, wt + WT_M1, DM, 4 * DM);
        dim3 gm2(DM / 32, 4 * DM / 32);
        transpose_kernel<<<gm2, 256>>>(mlp_w2, wt + WT_M2, 4 * DM, DM);
    }

    dim3 gN1(DM / 128, MTOK / 128);          // (8, 32)
    dim3 gN4(4 * DM / 128, MTOK / 128);      // (32, 32)
    dim3 gF(SEQ / 64, NH, BATCH);

    // x = LN1(tok_emb[tgt] + pos)
    embed_ln_kernel<<<MTOK, 256>>>(target_ids, tok_emb, pos_emb, ln1_g, ln1_b, xln);

    // self-attention
    gemm_bf16_kernel<<<gN1, 256, GEMM_SMEM>>>(xln, wt + WT_Q1, q1_b, nullptr, qb, MTOK, DM, DM, 0);
    gemm_bf16_kernel<<<gN1, 256, GEMM_SMEM>>>(xln, wt + WT_K1, k1_b, nullptr, kb, MTOK, DM, DM, 0);
    gemm_bf16_kernel<<<gN1, 256, GEMM_SMEM>>>(xln, wt + WT_V1, v1_b, nullptr, vb, MTOK, DM, DM, 0);
    flash_mma_kernel<<<gF, 128, FLASH_SMEM>>>(qb, kb, vb, target_ids, ab, 1);
    gemm_bf16_kernel<<<gN1, 256, GEMM_SMEM>>>(ab, wt + WT_O1, out1_b, xln, hb, MTOK, DM, DM, 2);

    // cross-attention (residual uses LN2 output, matching reference)
    ln_kernel<<<MTOK, 256>>>(hb, ln2_g, ln2_b, zb);
    gemm_bf16_kernel<<<gN1, 256, GEMM_SMEM>>>(zb, wt + WT_Q2, q2_b, nullptr, qb, MTOK, DM, DM, 0);
    gemm_bf16_kernel<<<gN1, 256, GEMM_SMEM>>>(input_embedding, wt + WT_K2, k2_b, nullptr, kb, MTOK, DM, DM, 0);
    gemm_bf16_kernel<<<gN1, 256, GEMM_SMEM>>>(input_embedding, wt + WT_V2, v2_b, nullptr, vb, MTOK, DM, DM, 0);
    flash_mma_kernel<<<gF, 128, FLASH_SMEM>>>(qb, kb, vb, input_ids, ab, 0);
    gemm_bf16_kernel<<<gN1, 256, GEMM_SMEM>>>(ab, wt + WT_O2, out2_b, zb, rb, MTOK, DM, DM, 2);

    // MLP
    ln_kernel<<<MTOK, 256>>>(rb, ln3_g, ln3_b, zb);
    gemm_bf16_kernel<<<gN4, 256, GEMM_SMEM>>>(zb, wt + WT_M1, mlp_b1, nullptr, tb, MTOK, 4 * DM, DM, 1);
    gemm_bf16_kernel<<<gN1, 256, GEMM_SMEM>>>(tb, wt + WT_M2, mlp_b2, rb, (float*)d_out, MTOK, DM, 4 * DM, 2);
}

// round 6
// speedup vs baseline: 1.9898x; 1.9898x over previous
#include <cuda_runtime.h>
#include <cuda_bf16.h>
#include <cuda_fp16.h>
#include <math.h>
#include <stdint.h>

#define SEQ    2048
#define BATCH  2
#define MTOK   4096      // BATCH*SEQ
#define DM     1024
#define NH     16
#define DHEAD  64
#define NEGV   -1000000000.0f

// -------- scratch (device globals; no allocation allowed) --------
__device__ float g_xln[MTOK * DM];          // LN1 out fp32
__device__ float g_xs [MTOK * DM];          // LN1 out bf16 split
__device__ float g_ies[MTOK * DM];          // input_embedding bf16 split
__device__ float g_qb [MTOK * DM];          // Q fp16 split
__device__ float g_kb [MTOK * DM];          // K fp16 split
__device__ float g_vb [MTOK * DM];          // V fp16 (half used)
__device__ float g_ab [MTOK * DM];          // attn out bf16 split
__device__ float g_hb [MTOK * DM];
__device__ float g_rb [MTOK * DM];
__device__ float g_zb [MTOK * DM];          // LN2/LN3 out fp32
__device__ float g_zs [MTOK * DM];          // LN2/LN3 out bf16 split
__device__ float g_tb [MTOK * 4 * DM];      // MLP mid bf16 split
__device__ float g_wt [16 * 1024 * 1024];   // transposed weights bf16 split [N][K]

#define WT_Q1   (0u)
#define WT_K1   (1u << 20)
#define WT_V1   (2u << 20)
#define WT_O1   (3u << 20)
#define WT_Q2   (4u << 20)
#define WT_K2   (5u << 20)
#define WT_V2   (6u << 20)
#define WT_O2   (7u << 20)
#define WT_M1   (8u << 20)   // [4096][1024]
#define WT_M2   (12u << 20)  // [1024][4096]

// ============================================================
// helpers
// ============================================================
__device__ __forceinline__ uint32_t smem_u32(const void* p) {
    uint32_t a;
    asm("{ .reg .u64 t; cvta.to.shared.u64 t, %1; cvt.u32.u64 %0, t; }"
        : "=r"(a) : "l"(p));
    return a;
}

#define LDSM_X4(r0, r1, r2, r3, addr) \
    asm volatile("ldmatrix.sync.aligned.m8n8.x4.shared.b16 {%0,%1,%2,%3}, [%4];" \
                 : "=r"(r0), "=r"(r1), "=r"(r2), "=r"(r3) : "r"(addr))

#define LDSM_X4_T(r0, r1, r2, r3, addr) \
    asm volatile("ldmatrix.sync.aligned.m8n8.x4.trans.shared.b16 {%0,%1,%2,%3}, [%4];" \
                 : "=r"(r0), "=r"(r1), "=r"(r2), "=r"(r3) : "r"(addr))

#define MMA_BF16(c, a, b0, b1) \
    asm volatile("mma.sync.aligned.m16n8k16.row.col.f32.bf16.bf16.f32 " \
                 "{%0,%1,%2,%3}, {%4,%5,%6,%7}, {%8,%9}, {%0,%1,%2,%3};" \
                 : "+f"((c)[0]), "+f"((c)[1]), "+f"((c)[2]), "+f"((c)[3]) \
                 : "r"((a)[0]), "r"((a)[1]), "r"((a)[2]), "r"((a)[3]), \
                   "r"(b0), "r"(b1))

#define MMA_F16(c, a, b0, b1) \
    asm volatile("mma.sync.aligned.m16n8k16.row.col.f32.f16.f16.f32 " \
                 "{%0,%1,%2,%3}, {%4,%5,%6,%7}, {%8,%9}, {%0,%1,%2,%3};" \
                 : "+f"((c)[0]), "+f"((c)[1]), "+f"((c)[2]), "+f"((c)[3]) \
                 : "r"((a)[0]), "r"((a)[1]), "r"((a)[2]), "r"((a)[3]), \
                   "r"(b0), "r"(b1))

#define CP_ASYNC16(dst, src) \
    asm volatile("cp.async.cg.shared.global [%0], [%1], 16;" \
                 :: "r"(dst), "l"(src) : "memory")
#define CP_COMMIT  asm volatile("cp.async.commit_group;" ::: "memory")
#define CP_WAIT0   asm volatile("cp.async.wait_group 0;" ::: "memory")

__device__ __forceinline__ uint32_t pack_h2(float a, float b) {
    __half2 h; h.x = __float2half(a); h.y = __float2half(b);
    return *(uint32_t*)&h;
}
__device__ __forceinline__ void bfsplit_store(__nv_bfloat16* hp, __nv_bfloat16* lp,
                                              float a, float b) {
    __nv_bfloat162 h = __floats2bfloat162_rn(a, b);
    __nv_bfloat162 l = __floats2bfloat162_rn(a - __bfloat162float(h.x),
                                             b - __bfloat162float(h.y));
    *(uint32_t*)hp = *(uint32_t*)&h;
    *(uint32_t*)lp = *(uint32_t*)&l;
}
__device__ __forceinline__ void hsplit_store(__half* hp, __half* lp,
                                             float a, float b) {
    __half ha = __float2half(a), hb = __float2half(b);
    __half2 h; h.x = ha; h.y = hb;
    __half2 l; l.x = __float2half(a - __half2float(ha));
    l.y = __float2half(b - __half2float(hb));
    *(uint32_t*)hp = *(uint32_t*)&h;
    *(uint32_t*)lp = *(uint32_t*)&l;
}

__device__ __forceinline__ float block_sum(float v, float* red) {
    int lane = threadIdx.x & 31, w = threadIdx.x >> 5;
    #pragma unroll
    for (int o = 16; o > 0; o >>= 1) v += __shfl_xor_sync(0xffffffffu, v, o);
    __syncthreads();
    if (lane == 0) red[w] = v;
    __syncthreads();
    if (w == 0) {
        float x = (lane < 8) ? red[lane] : 0.0f;
        #pragma unroll
        for (int o = 4; o > 0; o >>= 1) x += __shfl_xor_sync(0xffffffffu, x, o);
        if (lane == 0) red[0] = x;
    }
    __syncthreads();
    return red[0];
}
__device__ __forceinline__ float gelu_exact(float x) {
    return 0.5f * x * (1.0f + erff(x * 0.7071067811865475f));
}

// -------- weight transpose + bf16 split: WT[n][k] --------
__global__ __launch_bounds__(256) void transpose_split_kernel(
    const float* __restrict__ W, __nv_bfloat16* __restrict__ WThi, int K, int N)
{
    __shared__ float t[32][33];
    __nv_bfloat16* WTlo = WThi + (size_t)N * K;
    int n0 = blockIdx.x * 32, k0 = blockIdx.y * 32;
    int tx = threadIdx.x & 31, ty = threadIdx.x >> 5;
    #pragma unroll
    for (int i = 0; i < 4; i++)
        t[ty + 8 * i][tx] = W[(size_t)(k0 + ty + 8 * i) * N + n0 + tx];
    __syncthreads();
    #pragma unroll
    for (int i = 0; i < 4; i++) {
        float x = t[tx][ty + 8 * i];
        __nv_bfloat16 h = __float2bfloat16(x);
        __nv_bfloat16 l = __float2bfloat16(x - __bfloat162float(h));
        size_t o = (size_t)(n0 + ty + 8 * i) * K + k0 + tx;
        WThi[o] = h; WTlo[o] = l;
    }
}

// -------- plain bf16 split of an fp32 tensor --------
__global__ __launch_bounds__(256) void split_bf16_kernel(
    const float* __restrict__ X, __nv_bfloat16* __restrict__ Hi, int n)
{
    __nv_bfloat16* Lo = Hi + (size_t)n;
    int i = (blockIdx.x * 256 + threadIdx.x) * 4;
    float4 v = *(const float4*)(X + i);
    bfsplit_store(Hi + i,     Lo + i,     v.x, v.y);
    bfsplit_store(Hi + i + 2, Lo + i + 2, v.z, v.w);
}

// -------- fused embedding + LN1 (fp32 + bf16-split outs) --------
__global__ __launch_bounds__(256) void embed_ln_kernel(
    const int* __restrict__ ids, const float* __restrict__ tok,
    const float* __restrict__ pos, const float* __restrict__ gw,
    const float* __restrict__ bw, float* __restrict__ out,
    __nv_bfloat16* __restrict__ Shi)
{
    __shared__ float red[32];
    __nv_bfloat16* Slo = Shi + (size_t)MTOK * DM;
    int row = blockIdx.x;
    int s   = row & (SEQ - 1);
    int id  = ids[row];
    int d   = threadIdx.x * 4;
    float4 t4 = *(const float4*)(tok + (size_t)id * DM + d);
    float4 p4 = *(const float4*)(pos + (size_t)s  * DM + d);
    float4 v;
    v.x = t4.x + p4.x; v.y = t4.y + p4.y; v.z = t4.z + p4.z; v.w = t4.w + p4.w;
    float mu = block_sum(v.x + v.y + v.z + v.w, red) * (1.0f / DM);
    float dx = v.x - mu, dy = v.y - mu, dz = v.z - mu, dw = v.w - mu;
    float var = block_sum(dx*dx + dy*dy + dz*dz + dw*dw, red) * (1.0f / DM);
    float rstd = rsqrtf(var + 1e-5f);
    float4 o;
    o.x = dx * rstd * gw[d+0] + bw[d+0];
    o.y = dy * rstd * gw[d+1] + bw[d+1];
    o.z = dz * rstd * gw[d+2] + bw[d+2];
    o.w = dw * rstd * gw[d+3] + bw[d+3];
    size_t off = (size_t)row * DM + d;
    *(float4*)(out + off) = o;
    bfsplit_store(Shi + off,     Slo + off,     o.x, o.y);
    bfsplit_store(Shi + off + 2, Slo + off + 2, o.z, o.w);
}

// -------- plain LN (fp32 + bf16-split outs) --------
__global__ __launch_bounds__(256) void ln_kernel(
    const float* __restrict__ in, const float* __restrict__ gw,
    const float* __restrict__ bw, float* __restrict__ out,
    __nv_bfloat16* __restrict__ Shi)
{
    __shared__ float red[32];
    __nv_bfloat16* Slo = Shi + (size_t)MTOK * DM;
    int row = blockIdx.x;
    int d   = threadIdx.x * 4;
    float4 v = *(const float4*)(in + (size_t)row * DM + d);
    float mu = block_sum(v.x + v.y + v.z + v.w, red) * (1.0f / DM);
    float dx = v.x - mu, dy = v.y - mu, dz = v.z - mu, dw = v.w - mu;
    float var = block_sum(dx*dx + dy*dy + dz*dz + dw*dw, red) * (1.0f / DM);
    float rstd = rsqrtf(var + 1e-5f);
    float4 o;
    o.x = dx * rstd * gw[d+0] + bw[d+0];
    o.y = dy * rstd * gw[d+1] + bw[d+1];
    o.z = dz * rstd * gw[d+2] + bw[d+2];
    o.w = dw * rstd * gw[d+3] + bw[d+3];
    size_t off = (size_t)row * DM + d;
    *(float4*)(out + off) = o;
    bfsplit_store(Shi + off,     Slo + off,     o.x, o.y);
    bfsplit_store(Shi + off + 2, Slo + off + 2, o.z, o.w);
}

// ============================================================
// bf16x3-split GEMM, pre-split inputs, cp.async staging
// C = A*W + bias.  A: bf16 split [M][K] (lo at +M*K).
// WThi: bf16 split [N][K] (lo at +N*K).
// epi: 0 fp32 | 1 gelu->bf16split | 2 fp32+R | 3 fp16split | 4 fp16
// ============================================================
#define GTILE 10240
#define GEMM_SMEM (2 * 4 * GTILE)   // 81920

__global__ __launch_bounds__(256) void gemm_bf16_kernel(
    const __nv_bfloat16* __restrict__ Ahi, const __nv_bfloat16* __restrict__ WThi,
    const float* __restrict__ bias, const float* __restrict__ R,
    float* __restrict__ C, int M, int N, int K, int epi)
{
    extern __shared__ char smem[];
    const int tid = threadIdx.x, wid = tid >> 5, lane = tid & 31;
    const int m0 = blockIdx.y * 128, n0 = blockIdx.x * 128;
    const int warpM = (wid & 3) * 32, warpN = (wid >> 2) * 64;
    const uint32_t sb = smem_u32(smem);

    const __nv_bfloat16* Alo  = Ahi  + (size_t)M * K;
    const __nv_bfloat16* WTlo = WThi + (size_t)N * K;
    const __nv_bfloat16* srcs[4] = {
        Ahi + (size_t)m0 * K,  Alo + (size_t)m0 * K,
        WThi + (size_t)n0 * K, WTlo + (size_t)n0 * K };

    float acc[2][8][4];
    #pragma unroll
    for (int i = 0; i < 2; i++)
        #pragma unroll
        for (int j = 0; j < 8; j++)
            #pragma unroll
            for (int q = 0; q < 4; q++) acc[i][j][q] = 0.0f;

    const int a_stat = (warpM + ((lane >> 3) & 1) * 8 + (lane & 7)) * 40 + (lane >> 4) * 8;
    const int b_stat = (warpN + ((lane >> 4) & 1) * 8 + (lane & 7)) * 40 + ((lane >> 3) & 1) * 8;
    const int NKB = K >> 5;

#define G_ISSUE(kb, buf) { \
    _Pragma("unroll") for (int i = 0; i < 8; i++) { \
        const int tile = i >> 1; \
        int r = ((tid >> 2) + 64 * i) & 127; \
        int s = tid & 3; \
        const __nv_bfloat16* src = srcs[tile] + (size_t)r * K + (kb) * 32 + s * 8; \
        uint32_t dst = sb + (buf) * 40960 + tile * GTILE + (uint32_t)(r * 40 + s * 8) * 2; \
        CP_ASYNC16(dst, src); \
    } \
    CP_COMMIT; }

#define G_COMPUTE(buf) { \
    uint32_t tb0 = sb + (buf) * 40960; \
    _Pragma("unroll") for (int ks = 0; ks < 2; ks++) { \
        const int Cc = ks * 16; \
        uint32_t fa[2][4], fl[2][4], bh[4][4], bl[4][4]; \
        _Pragma("unroll") for (int mb = 0; mb < 2; mb++) { \
            uint32_t ad = tb0 + (uint32_t)(a_stat + mb * 640 + Cc) * 2; \
            LDSM_X4(fa[mb][0], fa[mb][1], fa[mb][2], fa[mb][3], ad); \
            LDSM_X4(fl[mb][0], fl[mb][1], fl[mb][2], fl[mb][3], ad + GTILE); \
        } \
        _Pragma("unroll") for (int p = 0; p < 4; p++) { \
            uint32_t bd = tb0 + 2 * GTILE + (uint32_t)(b_stat + p * 640 + Cc) * 2; \
            LDSM_X4(bh[p][0], bh[p][1], bh[p][2], bh[p][3], bd); \
            LDSM_X4(bl[p][0], bl[p][1], bl[p][2], bl[p][3], bd + GTILE); \
        } \
        _Pragma("unroll") for (int mb = 0; mb < 2; mb++) \
        _Pragma("unroll") for (int nb = 0; nb < 8; nb++) { \
            const int p = nb >> 1, q = (nb & 1) * 2; \
            MMA_BF16(acc[mb][nb], fa[mb], bh[p][q], bh[p][q + 1]); \
            MMA_BF16(acc[mb][nb], fa[mb], bl[p][q], bl[p][q + 1]); \
            MMA_BF16(acc[mb][nb], fl[mb], bh[p][q], bh[p][q + 1]); \
        } } }

    G_ISSUE(0, 0);
    CP_WAIT0;
    __syncthreads();

    for (int kb = 0; kb < NKB; kb++) {
        if (kb + 1 < NKB) G_ISSUE(kb + 1, (kb + 1) & 1);
        G_COMPUTE(kb & 1);
        if (kb + 1 < NKB) {
            CP_WAIT0;
            __syncthreads();
        }
    }

    // epilogue
    const int g = lane >> 2, t = lane & 3;
    #pragma unroll
    for (int mb = 0; mb < 2; mb++)
        #pragma unroll
        for (int nb = 0; nb < 8; nb++) {
            int row = m0 + warpM + mb * 16 + g;
            int col = n0 + warpN + nb * 8 + 2 * t;
            float2 b2 = *(const float2*)(bias + col);
            float v0 = acc[mb][nb][0] + b2.x, v1 = acc[mb][nb][1] + b2.y;
            float v2 = acc[mb][nb][2] + b2.x, v3 = acc[mb][nb][3] + b2.y;
            size_t o0 = (size_t)row * N + col, o1 = (size_t)(row + 8) * N + col;
            if (epi == 0 || epi == 2) {
                if (epi == 2) {
                    float2 r0 = *(const float2*)(R + o0);
                    float2 r1 = *(const float2*)(R + o1);
                    v0 += r0.x; v1 += r0.y; v2 += r1.x; v3 += r1.y;
                }
                float2 c0 = {v0, v1}, c1 = {v2, v3};
                *(float2*)(C + o0) = c0;
                *(float2*)(C + o1) = c1;
            } else if (epi == 1) {
                v0 = gelu_exact(v0); v1 = gelu_exact(v1);
                v2 = gelu_exact(v2); v3 = gelu_exact(v3);
                __nv_bfloat16* Chi = (__nv_bfloat16*)C;
                __nv_bfloat16* Clo = Chi + (size_t)M * N;
                bfsplit_store(Chi + o0, Clo + o0, v0, v1);
                bfsplit_store(Chi + o1, Clo + o1, v2, v3);
            } else if (epi == 3) {
                __half* Chi = (__half*)C;
                __half* Clo = Chi + (size_t)M * N;
                hsplit_store(Chi + o0, Clo + o0, v0, v1);
                hsplit_store(Chi + o1, Clo + o1, v2, v3);
            } else {
                __half* Ch = (__half*)C;
                *(uint32_t*)(Ch + o0) = pack_h2(v0, v1);
                *(uint32_t*)(Ch + o1) = pack_h2(v2, v3);
            }
        }
}

// ============================================================
// flash attention, pre-split fp16 Q/K (x3), fp16 V; cp.async staging
// 128 threads / 4 warps; BQ=64 (16 rows/warp); BK=64
// smem: Khi[64][72] | Klo[64][72] | V[64][72] | nadd[64]
// ============================================================
#define FS 72
#define FOFF_KLO 9216
#define FOFF_VT  18432
#define FOFF_NAD 27648
#define FLASH_SMEM (27648 + 256)

__global__ __launch_bounds__(128) void flash_mma_kernel(
    const __half* __restrict__ Qhi, const __half* __restrict__ Khi,
    const __half* __restrict__ Vf, const int* __restrict__ ids,
    __nv_bfloat16* __restrict__ Ohi, int causal)
{
    extern __shared__ char fsm[];
    const uint32_t sb = smem_u32(fsm);
    float* nadd = (float*)(fsm + FOFF_NAD);

    const int tid = threadIdx.x, wid = tid >> 5, lane = tid & 31;
    const int qt = blockIdx.x, h = blockIdx.y, b = blockIdx.z;
    const int qbase = qt * 64;
    const int g = lane >> 2, t = lane & 3;

    const __half* Qlo = Qhi + (size_t)MTOK * DM;
    const __half* Klo = Khi + (size_t)MTOK * DM;
    __nv_bfloat16* Olo = Ohi + (size_t)MTOK * DM;

    const __half* Qph = Qhi + (size_t)b * SEQ * DM + h * DHEAD;
    const __half* Qpl = Qlo + (size_t)b * SEQ * DM + h * DHEAD;
    const __half* Kph = Khi + (size_t)b * SEQ * DM + h * DHEAD;
    const __half* Kpl = Klo + (size_t)b * SEQ * DM + h * DHEAD;
    const __half* Vp  = Vf  + (size_t)b * SEQ * DM + h * DHEAD;

    // ---- stage Q into K region (hi@0, lo@FOFF_KLO) ----
    #pragma unroll
    for (int i = 0; i < 8; i++) {
        const int arr = i >> 2;
        int r = (16 * i + (tid >> 3)) & 63;
        int s = tid & 7;
        const __half* src = (arr ? Qpl : Qph) + (size_t)(qbase + r) * DM + s * 8;
        uint32_t dst = sb + arr * FOFF_KLO + (uint32_t)(r * FS + s * 8) * 2;
        CP_ASYNC16(dst, src);
    }
    CP_COMMIT; CP_WAIT0;
    __syncthreads();

    // ---- Q fragments to registers ----
    uint32_t qh[4][4], ql[4][4];
    {
        int arow = (lane & 15) + 16 * wid;
        int acb  = ((lane >> 4) & 1) * 8;
        #pragma unroll
        for (int kk = 0; kk < 4; kk++) {
            uint32_t ad = sb + (uint32_t)(arow * FS + acb + kk * 16) * 2;
            LDSM_X4(qh[kk][0], qh[kk][1], qh[kk][2], qh[kk][3], ad);
            LDSM_X4(ql[kk][0], ql[kk][1], ql[kk][2], ql[kk][3], ad + FOFF_KLO);
        }
    }

    float mA = -3.0e38f, mB = -3.0e38f, lA = 0.0f, lB = 0.0f;
    float O[8][4];
    #pragma unroll
    for (int nb = 0; nb < 8; nb++)
        #pragma unroll
        for (int q = 0; q < 4; q++) O[nb][q] = 0.0f;

    const int rowA = qbase + 16 * wid + g;
    const int nkt = causal ? (qt + 1) : (SEQ / 64);

    for (int kt = 0; kt < nkt; kt++) {
        const int kbase = kt * 64;
        const bool diag = causal && (kt == qt);
        __syncthreads();   // previous-tile reads complete before overwrite

        // stage K (hi/lo) + V via cp.async
        #pragma unroll
        for (int i = 0; i < 8; i++) {
            const int arr = i >> 2;
            int r = (16 * i + (tid >> 3)) & 63;
            int s = tid & 7;
            const __half* src = (arr ? Kpl : Kph) + (size_t)(kbase + r) * DM + s * 8;
            uint32_t dst = sb + arr * FOFF_KLO + (uint32_t)(r * FS + s * 8) * 2;
            CP_ASYNC16(dst, src);
        }
        #pragma unroll
        for (int i = 0; i < 4; i++) {
            int r = (16 * i + (tid >> 3)) & 63;
            int s = tid & 7;
            const __half* src = Vp + (size_t)(kbase + r) * DM + s * 8;
            uint32_t dst = sb + FOFF_VT + (uint32_t)(r * FS + s * 8) * 2;
            CP_ASYNC16(dst, src);
        }
        if (tid < 64)
            nadd[tid] = (ids[b * SEQ + kbase + tid] == 0) ? NEGV : 0.0f;
        CP_COMMIT; CP_WAIT0;
        __syncthreads();

        // ---- S = Q K^T (fp16x3) ----
        float sc[8][4];
        #pragma unroll
        for (int nb = 0; nb < 8; nb++)
            #pragma unroll
            for (int q = 0; q < 4; q++) sc[nb][q] = 0.0f;

        #pragma unroll
        for (int kk = 0; kk < 4; kk++) {
            #pragma unroll
            for (int p = 0; p < 4; p++) {
                int brow = p * 16 + ((lane >> 4) & 1) * 8 + (lane & 7);
                int bcol = kk * 16 + ((lane >> 3) & 1) * 8;
                uint32_t bd = sb + (uint32_t)(brow * FS + bcol) * 2;
                uint32_t bh[4], bl[4];
                LDSM_X4(bh[0], bh[1], bh[2], bh[3], bd);
                LDSM_X4(bl[0], bl[1], bl[2], bl[3], bd + FOFF_KLO);
                MMA_F16(sc[2*p],   qh[kk], bh[0], bh[1]);
                MMA_F16(sc[2*p],   qh[kk], bl[0], bl[1]);
                MMA_F16(sc[2*p],   ql[kk], bh[0], bh[1]);
                MMA_F16(sc[2*p+1], qh[kk], bh[2], bh[3]);
                MMA_F16(sc[2*p+1], qh[kk], bl[2], bl[3]);
                MMA_F16(sc[2*p+1], ql[kk], bh[2], bh[3]);
            }
        }

        // ---- scale + masks + online softmax ----
        float rmaxA = -3.0e38f, rmaxB = -3.0e38f;
        #pragma unroll
        for (int nb = 0; nb < 8; nb++) {
            int col0 = kbase + nb * 8 + 2 * t;
            float p0 = nadd[nb * 8 + 2 * t], p1 = nadd[nb * 8 + 2 * t + 1];
            float v0 = sc[nb][0] * 0.125f + p0;
            float v1 = sc[nb][1] * 0.125f + p1;
            float v2 = sc[nb][2] * 0.125f + p0;
            float v3 = sc[nb][3] * 0.125f + p1;
            if (diag) {
                if (col0     > rowA)     v0 += NEGV;
                if (col0 + 1 > rowA)     v1 += NEGV;
                if (col0     > rowA + 8) v2 += NEGV;
                if (col0 + 1 > rowA + 8) v3 += NEGV;
            }
            sc[nb][0] = v0; sc[nb][1] = v1; sc[nb][2] = v2; sc[nb][3] = v3;
            rmaxA = fmaxf(rmaxA, fmaxf(v0, v1));
            rmaxB = fmaxf(rmaxB, fmaxf(v2, v3));
        }
        #pragma unroll
        for (int o = 1; o <= 2; o <<= 1) {
            rmaxA = fmaxf(rmaxA, __shfl_xor_sync(0xffffffffu, rmaxA, o));
            rmaxB = fmaxf(rmaxB, __shfl_xor_sync(0xffffffffu, rmaxB, o));
        }
        float mnA = fmaxf(mA, rmaxA), mnB = fmaxf(mB, rmaxB);
        float aA = __expf(mA - mnA), aB = __expf(mB - mnB);
        mA = mnA; mB = mnB;

        uint32_t af[4][4];
        float sA = 0.0f, sB = 0.0f;
        #pragma unroll
        for (int nb = 0; nb < 8; nb++) {
            float p0 = __expf(sc[nb][0] - mnA);
            float p1 = __expf(sc[nb][1] - mnA);
            float p2 = __expf(sc[nb][2] - mnB);
            float p3 = __expf(sc[nb][3] - mnB);
            __half h0 = __float2half(p0), h1 = __float2half(p1);
            __half h2 = __float2half(p2), h3 = __float2half(p3);
            sA += __half2float(h0) + __half2float(h1);
            sB += __half2float(h2) + __half2float(h3);
            __half2 u01; u01.x = h0; u01.y = h1;
            __half2 u23; u23.x = h2; u23.y = h3;
            int kk = nb >> 1, hi = nb & 1;
            af[kk][hi * 2 + 0] = *(uint32_t*)&u01;
            af[kk][hi * 2 + 1] = *(uint32_t*)&u23;
        }
        #pragma unroll
        for (int o = 1; o <= 2; o <<= 1) {
            sA += __shfl_xor_sync(0xffffffffu, sA, o);
            sB += __shfl_xor_sync(0xffffffffu, sB, o);
        }
        lA = lA * aA + sA; lB = lB * aB + sB;
        #pragma unroll
        for (int nb = 0; nb < 8; nb++) {
            O[nb][0] *= aA; O[nb][1] *= aA;
            O[nb][2] *= aB; O[nb][3] *= aB;
        }

        // ---- O += P V (ldmatrix.trans on row-major V) ----
        #pragma unroll
        for (int kk = 0; kk < 4; kk++) {
            #pragma unroll
            for (int nbp = 0; nbp < 4; nbp++) {
                int vrow = kk * 16 + (lane & 15);
                int vcol = nbp * 16 + (lane >> 4) * 8;
                uint32_t bd = sb + FOFF_VT + (uint32_t)(vrow * FS + vcol) * 2;
                uint32_t v0, v1, v2, v3;
                LDSM_X4_T(v0, v1, v2, v3, bd);
                MMA_F16(O[2*nbp],     af[kk], v0, v1);
                MMA_F16(O[2*nbp + 1], af[kk], v2, v3);
            }
        }
    }

    // ---- write out (bf16 split for next GEMM's A) ----
    float iA = 1.0f / lA, iB = 1.0f / lB;
    #pragma unroll
    for (int nb = 0; nb < 8; nb++) {
        int col = h * DHEAD + nb * 8 + 2 * t;
        size_t off0 = ((size_t)b * SEQ + rowA) * DM + col;
        size_t off1 = ((size_t)b * SEQ + rowA + 8) * DM + col;
        bfsplit_store(Ohi + off0, Olo + off0, O[nb][0] * iA, O[nb][1] * iA);
        bfsplit_store(Ohi + off1, Olo + off1, O[nb][2] * iB, O[nb][3] * iB);
    }
}

// ============================================================
// host pipeline
// ============================================================
extern "C" void kernel_launch(void* const* d_in, const int* in_sizes, int n_in,
                              void* d_out, int out_size)
{
    const float* input_embedding = (const float*)d_in[0];
    const int*   input_ids       = (const int*)  d_in[1];
    const int*   target_ids      = (const int*)  d_in[2];
    const float* tok_emb = (const float*)d_in[3];
    const float* pos_emb = (const float*)d_in[4];
    const float* ln1_g = (const float*)d_in[5],  *ln1_b = (const float*)d_in[6];
    const float* q1_w  = (const float*)d_in[7],  *q1_b  = (const float*)d_in[8];
    const float* k1_w  = (const float*)d_in[9],  *k1_b  = (const float*)d_in[10];
    const float* v1_w  = (const float*)d_in[11], *v1_b  = (const float*)d_in[12];
    const float* out1_w= (const float*)d_in[13], *out1_b= (const float*)d_in[14];
    const float* ln2_g = (const float*)d_in[15], *ln2_b = (const float*)d_in[16];
    const float* q2_w  = (const float*)d_in[17], *q2_b  = (const float*)d_in[18];
    const float* k2_w  = (const float*)d_in[19], *k2_b  = (const float*)d_in[20];
    const float* v2_w  = (const float*)d_in[21], *v2_b  = (const float*)d_in[22];
    const float* out2_w= (const float*)d_in[23], *out2_b= (const float*)d_in[24];
    const float* ln3_g = (const float*)d_in[25], *ln3_b = (const float*)d_in[26];
    const float* mlp_w1= (const float*)d_in[27], *mlp_b1= (const float*)d_in[28];
    const float* mlp_w2= (const float*)d_in[29], *mlp_b2= (const float*)d_in[30];

    float *xln, *xs, *ies, *qb, *kb, *vb, *ab, *hb, *rb, *zb, *zs, *tb, *wt;
    cudaGetSymbolAddress((void**)&xln, g_xln);
    cudaGetSymbolAddress((void**)&xs,  g_xs);
    cudaGetSymbolAddress((void**)&ies, g_ies);
    cudaGetSymbolAddress((void**)&qb,  g_qb);
    cudaGetSymbolAddress((void**)&kb,  g_kb);
    cudaGetSymbolAddress((void**)&vb,  g_vb);
    cudaGetSymbolAddress((void**)&ab,  g_ab);
    cudaGetSymbolAddress((void**)&hb,  g_hb);
    cudaGetSymbolAddress((void**)&rb,  g_rb);
    cudaGetSymbolAddress((void**)&zb,  g_zb);
    cudaGetSymbolAddress((void**)&zs,  g_zs);
    cudaGetSymbolAddress((void**)&tb,  g_tb);
    cudaGetSymbolAddress((void**)&wt,  g_wt);

    cudaFuncSetAttribute(gemm_bf16_kernel,
                         cudaFuncAttributeMaxDynamicSharedMemorySize, GEMM_SMEM);

    // ---- one-time prep: weight transpose+split, input_embedding split ----
    {
        dim3 g1(DM / 32, DM / 32);
        transpose_split_kernel<<<g1, 256>>>(q1_w,  (__nv_bfloat16*)(wt + WT_Q1), DM, DM);
        transpose_split_kernel<<<g1, 256>>>(k1_w,  (__nv_bfloat16*)(wt + WT_K1), DM, DM);
        transpose_split_kernel<<<g1, 256>>>(v1_w,  (__nv_bfloat16*)(wt + WT_V1), DM, DM);
        transpose_split_kernel<<<g1, 256>>>(out1_w,(__nv_bfloat16*)(wt + WT_O1), DM, DM);
        transpose_split_kernel<<<g1, 256>>>(q2_w,  (__nv_bfloat16*)(wt + WT_Q2), DM, DM);
        transpose_split_kernel<<<g1, 256>>>(k2_w,  (__nv_bfloat16*)(wt + WT_K2), DM, DM);
        transpose_split_kernel<<<g1, 256>>>(v2_w,  (__nv_bfloat16*)(wt + WT_V2), DM, DM);
        transpose_split_kernel<<<g1, 256>>>(out2_w,(__nv_bfloat16*)(wt + WT_O2), DM, DM);
        dim3 gm1(4 * DM / 32, DM / 32);
        transpose_split_kernel<<<gm1, 256>>>(mlp_w1, (__nv_bfloat16*)(wt + WT_M1), DM, 4 * DM);
        dim3 gm2(DM / 32, 4 * DM / 32);
        transpose_split_kernel<<<gm2, 256>>>(mlp_w2, (__nv_bfloat16*)(wt + WT_M2), 4 * DM, DM);
        split_bf16_kernel<<<MTOK * DM / 1024, 256>>>(input_embedding,
                                                     (__nv_bfloat16*)ies, MTOK * DM);
    }

    dim3 gN1(DM / 128, MTOK / 128);          // (8, 32)
    dim3 gN4(4 * DM / 128, MTOK / 128);      // (32, 32)
    dim3 gF(SEQ / 64, NH, BATCH);

    // x = LN1(tok_emb[tgt] + pos)  -> xln (fp32) + xs (bf16 split)
    embed_ln_kernel<<<MTOK, 256>>>(target_ids, tok_emb, pos_emb, ln1_g, ln1_b,
                                   xln, (__nv_bfloat16*)xs);

    // self-attention
    gemm_bf16_kernel<<<gN1, 256, GEMM_SMEM>>>((const __nv_bfloat16*)xs,
        (const __nv_bfloat16*)(wt + WT_Q1), q1_b, nullptr, qb, MTOK, DM, DM, 3);
    gemm_bf16_kernel<<<gN1, 256, GEMM_SMEM>>>((const __nv_bfloat16*)xs,
        (const __nv_bfloat16*)(wt + WT_K1), k1_b, nullptr, kb, MTOK, DM, DM, 3);
    gemm_bf16_kernel<<<gN1, 256, GEMM_SMEM>>>((const __nv_bfloat16*)xs,
        (const __nv_bfloat16*)(wt + WT_V1), v1_b, nullptr, vb, MTOK, DM, DM, 4);
    flash_mma_kernel<<<gF, 128, FLASH_SMEM>>>((const __half*)qb, (const __half*)kb,
        (const __half*)vb, target_ids, (__nv_bfloat16*)ab, 1);
    gemm_bf16_kernel<<<gN1, 256, GEMM_SMEM>>>((const __nv_bfloat16*)ab,
        (const __nv_bfloat16*)(wt + WT_O1), out1_b, xln, hb, MTOK, DM, DM, 2);

    // cross-attention (residual uses LN2 output, matching reference)
    ln_kernel<<<MTOK, 256>>>(hb, ln2_g, ln2_b, zb, (__nv_bfloat16*)zs);
    gemm_bf16_kernel<<<gN1, 256, GEMM_SMEM>>>((const __nv_bfloat16*)zs,
        (const __nv_bfloat16*)(wt + WT_Q2), q2_b, nullptr, qb, MTOK, DM, DM, 3);
    gemm_bf16_kernel<<<gN1, 256, GEMM_SMEM>>>((const __nv_bfloat16*)ies,
        (const __nv_bfloat16*)(wt + WT_K2), k2_b, nullptr, kb, MTOK, DM, DM, 3);
    gemm_bf16_kernel<<<gN1, 256, GEMM_SMEM>>>((const __nv_bfloat16*)ies,
        (const __nv_bfloat16*)(wt + WT_V2), v2_b, nullptr, vb, MTOK, DM, DM, 4);
    flash_mma_kernel<<<gF, 128, FLASH_SMEM>>>((const __half*)qb, (const __half*)kb,
        (const __half*)vb, input_ids, (__nv_bfloat16*)ab, 0);
    gemm_bf16_kernel<<<gN1, 256, GEMM_SMEM>>>((const __nv_bfloat16*)ab,
        (const __nv_bfloat16*)(wt + WT_O2), out2_b, zb, rb, MTOK, DM, DM, 2);

    // MLP
    ln_kernel<<<MTOK, 256>>>(rb, ln3_g, ln3_b, zb, (__nv_bfloat16*)zs);
    gemm_bf16_kernel<<<gN4, 256, GEMM_SMEM>>>((const __nv_bfloat16*)zs,
        (const __nv_bfloat16*)(wt + WT_M1), mlp_b1, nullptr, tb, MTOK, 4 * DM, DM, 1);
    gemm_bf16_kernel<<<gN1, 256, GEMM_SMEM>>>((const __nv_bfloat16*)tb,
        (const __nv_bfloat16*)(wt + WT_M2), mlp_b2, rb, (float*)d_out, MTOK, DM, 4 * DM, 2);
}

// round 7
// speedup vs baseline: 2.0345x; 1.0225x over previous
#include <cuda_runtime.h>
#include <cuda_bf16.h>
#include <cuda_fp16.h>
#include <math.h>
#include <stdint.h>

#define SEQ    2048
#define BATCH  2
#define MTOK   4096      // BATCH*SEQ
#define DM     1024
#define NH     16
#define DHEAD  64
#define NEGV   -1000000000.0f

// -------- scratch (device globals; no allocation allowed) --------
__device__ float g_xln[MTOK * DM];          // LN1 out fp32
__device__ float g_xs [MTOK * DM];          // LN1 out bf16 split
__device__ float g_ies[MTOK * DM];          // input_embedding bf16 split
__device__ float g_qb [MTOK * DM];          // Q fp16 split
__device__ float g_kb [MTOK * DM];          // K fp16 split
__device__ float g_vb [MTOK * DM];          // V fp16 (half used)
__device__ float g_ab [MTOK * DM];          // attn out bf16 split
__device__ float g_hb [MTOK * DM];
__device__ float g_rb [MTOK * DM];
__device__ float g_zb [MTOK * DM];          // LN2/LN3 out fp32
__device__ float g_zs [MTOK * DM];          // LN2/LN3 out bf16 split
__device__ float g_tb [MTOK * 4 * DM];      // MLP mid bf16 split
__device__ float g_wt [16 * 1024 * 1024];   // transposed weights bf16 split [N][K]

#define WT_Q1   (0u)
#define WT_K1   (1u << 20)
#define WT_V1   (2u << 20)
#define WT_O1   (3u << 20)
#define WT_Q2   (4u << 20)
#define WT_K2   (5u << 20)
#define WT_V2   (6u << 20)
#define WT_O2   (7u << 20)
#define WT_M1   (8u << 20)   // [4096][1024]
#define WT_M2   (12u << 20)  // [1024][4096]

// ============================================================
// helpers
// ============================================================
__device__ __forceinline__ uint32_t smem_u32(const void* p) {
    uint32_t a;
    asm("{ .reg .u64 t; cvta.to.shared.u64 t, %1; cvt.u32.u64 %0, t; }"
        : "=r"(a) : "l"(p));
    return a;
}

#define LDSM_X4(r0, r1, r2, r3, addr) \
    asm volatile("ldmatrix.sync.aligned.m8n8.x4.shared.b16 {%0,%1,%2,%3}, [%4];" \
                 : "=r"(r0), "=r"(r1), "=r"(r2), "=r"(r3) : "r"(addr))

#define LDSM_X4_T(r0, r1, r2, r3, addr) \
    asm volatile("ldmatrix.sync.aligned.m8n8.x4.trans.shared.b16 {%0,%1,%2,%3}, [%4];" \
                 : "=r"(r0), "=r"(r1), "=r"(r2), "=r"(r3) : "r"(addr))

#define MMA_BF16(c, a, b0, b1) \
    asm volatile("mma.sync.aligned.m16n8k16.row.col.f32.bf16.bf16.f32 " \
                 "{%0,%1,%2,%3}, {%4,%5,%6,%7}, {%8,%9}, {%0,%1,%2,%3};" \
                 : "+f"((c)[0]), "+f"((c)[1]), "+f"((c)[2]), "+f"((c)[3]) \
                 : "r"((a)[0]), "r"((a)[1]), "r"((a)[2]), "r"((a)[3]), \
                   "r"(b0), "r"(b1))

#define MMA_F16(c, a, b0, b1) \
    asm volatile("mma.sync.aligned.m16n8k16.row.col.f32.f16.f16.f32 " \
                 "{%0,%1,%2,%3}, {%4,%5,%6,%7}, {%8,%9}, {%0,%1,%2,%3};" \
                 : "+f"((c)[0]), "+f"((c)[1]), "+f"((c)[2]), "+f"((c)[3]) \
                 : "r"((a)[0]), "r"((a)[1]), "r"((a)[2]), "r"((a)[3]), \
                   "r"(b0), "r"(b1))

#define CP_ASYNC16(dst, src) \
    asm volatile("cp.async.cg.shared.global [%0], [%1], 16;" \
                 :: "r"(dst), "l"(src) : "memory")
#define CP_COMMIT  asm volatile("cp.async.commit_group;" ::: "memory")
#define CP_WAIT0   asm volatile("cp.async.wait_group 0;" ::: "memory")

__device__ __forceinline__ uint32_t pack_h2(float a, float b) {
    __half2 h; h.x = __float2half(a); h.y = __float2half(b);
    return *(uint32_t*)&h;
}
__device__ __forceinline__ void bfsplit_store(__nv_bfloat16* hp, __nv_bfloat16* lp,
                                              float a, float b) {
    __nv_bfloat162 h = __floats2bfloat162_rn(a, b);
    __nv_bfloat162 l = __floats2bfloat162_rn(a - __bfloat162float(h.x),
                                             b - __bfloat162float(h.y));
    *(uint32_t*)hp = *(uint32_t*)&h;
    *(uint32_t*)lp = *(uint32_t*)&l;
}
__device__ __forceinline__ void hsplit_store(__half* hp, __half* lp,
                                             float a, float b) {
    __half ha = __float2half(a), hb = __float2half(b);
    __half2 h; h.x = ha; h.y = hb;
    __half2 l; l.x = __float2half(a - __half2float(ha));
    l.y = __float2half(b - __half2float(hb));
    *(uint32_t*)hp = *(uint32_t*)&h;
    *(uint32_t*)lp = *(uint32_t*)&l;
}

__device__ __forceinline__ float block_sum(float v, float* red) {
    int lane = threadIdx.x & 31, w = threadIdx.x >> 5;
    #pragma unroll
    for (int o = 16; o > 0; o >>= 1) v += __shfl_xor_sync(0xffffffffu, v, o);
    __syncthreads();
    if (lane == 0) red[w] = v;
    __syncthreads();
    if (w == 0) {
        float x = (lane < 8) ? red[lane] : 0.0f;
        #pragma unroll
        for (int o = 4; o > 0; o >>= 1) x += __shfl_xor_sync(0xffffffffu, x, o);
        if (lane == 0) red[0] = x;
    }
    __syncthreads();
    return red[0];
}
__device__ __forceinline__ float gelu_exact(float x) {
    return 0.5f * x * (1.0f + erff(x * 0.7071067811865475f));
}

// -------- weight transpose + bf16 split: WT[n][k] --------
__global__ __launch_bounds__(256) void transpose_split_kernel(
    const float* __restrict__ W, __nv_bfloat16* __restrict__ WThi, int K, int N)
{
    __shared__ float t[32][33];
    __nv_bfloat16* WTlo = WThi + (size_t)N * K;
    int n0 = blockIdx.x * 32, k0 = blockIdx.y * 32;
    int tx = threadIdx.x & 31, ty = threadIdx.x >> 5;
    #pragma unroll
    for (int i = 0; i < 4; i++)
        t[ty + 8 * i][tx] = W[(size_t)(k0 + ty + 8 * i) * N + n0 + tx];
    __syncthreads();
    #pragma unroll
    for (int i = 0; i < 4; i++) {
        float x = t[tx][ty + 8 * i];
        __nv_bfloat16 h = __float2bfloat16(x);
        __nv_bfloat16 l = __float2bfloat16(x - __bfloat162float(h));
        size_t o = (size_t)(n0 + ty + 8 * i) * K + k0 + tx;
        WThi[o] = h; WTlo[o] = l;
    }
}

// -------- plain bf16 split of an fp32 tensor --------
__global__ __launch_bounds__(256) void split_bf16_kernel(
    const float* __restrict__ X, __nv_bfloat16* __restrict__ Hi, int n)
{
    __nv_bfloat16* Lo = Hi + (size_t)n;
    int i = (blockIdx.x * 256 + threadIdx.x) * 4;
    float4 v = *(const float4*)(X + i);
    bfsplit_store(Hi + i,     Lo + i,     v.x, v.y);
    bfsplit_store(Hi + i + 2, Lo + i + 2, v.z, v.w);
}

// -------- fused embedding + LN1 (fp32 + bf16-split outs) --------
__global__ __launch_bounds__(256) void embed_ln_kernel(
    const int* __restrict__ ids, const float* __restrict__ tok,
    const float* __restrict__ pos, const float* __restrict__ gw,
    const float* __restrict__ bw, float* __restrict__ out,
    __nv_bfloat16* __restrict__ Shi)
{
    __shared__ float red[32];
    __nv_bfloat16* Slo = Shi + (size_t)MTOK * DM;
    int row = blockIdx.x;
    int s   = row & (SEQ - 1);
    int id  = ids[row];
    int d   = threadIdx.x * 4;
    float4 t4 = *(const float4*)(tok + (size_t)id * DM + d);
    float4 p4 = *(const float4*)(pos + (size_t)s  * DM + d);
    float4 v;
    v.x = t4.x + p4.x; v.y = t4.y + p4.y; v.z = t4.z + p4.z; v.w = t4.w + p4.w;
    float mu = block_sum(v.x + v.y + v.z + v.w, red) * (1.0f / DM);
    float dx = v.x - mu, dy = v.y - mu, dz = v.z - mu, dw = v.w - mu;
    float var = block_sum(dx*dx + dy*dy + dz*dz + dw*dw, red) * (1.0f / DM);
    float rstd = rsqrtf(var + 1e-5f);
    float4 o;
    o.x = dx * rstd * gw[d+0] + bw[d+0];
    o.y = dy * rstd * gw[d+1] + bw[d+1];
    o.z = dz * rstd * gw[d+2] + bw[d+2];
    o.w = dw * rstd * gw[d+3] + bw[d+3];
    size_t off = (size_t)row * DM + d;
    *(float4*)(out + off) = o;
    bfsplit_store(Shi + off,     Slo + off,     o.x, o.y);
    bfsplit_store(Shi + off + 2, Slo + off + 2, o.z, o.w);
}

// -------- plain LN (fp32 + bf16-split outs) --------
__global__ __launch_bounds__(256) void ln_kernel(
    const float* __restrict__ in, const float* __restrict__ gw,
    const float* __restrict__ bw, float* __restrict__ out,
    __nv_bfloat16* __restrict__ Shi)
{
    __shared__ float red[32];
    __nv_bfloat16* Slo = Shi + (size_t)MTOK * DM;
    int row = blockIdx.x;
    int d   = threadIdx.x * 4;
    float4 v = *(const float4*)(in + (size_t)row * DM + d);
    float mu = block_sum(v.x + v.y + v.z + v.w, red) * (1.0f / DM);
    float dx = v.x - mu, dy = v.y - mu, dz = v.z - mu, dw = v.w - mu;
    float var = block_sum(dx*dx + dy*dy + dz*dz + dw*dw, red) * (1.0f / DM);
    float rstd = rsqrtf(var + 1e-5f);
    float4 o;
    o.x = dx * rstd * gw[d+0] + bw[d+0];
    o.y = dy * rstd * gw[d+1] + bw[d+1];
    o.z = dz * rstd * gw[d+2] + bw[d+2];
    o.w = dw * rstd * gw[d+3] + bw[d+3];
    size_t off = (size_t)row * DM + d;
    *(float4*)(out + off) = o;
    bfsplit_store(Shi + off,     Slo + off,     o.x, o.y);
    bfsplit_store(Shi + off + 2, Slo + off + 2, o.z, o.w);
}

// ============================================================
// bf16x3-split GEMM, pre-split inputs, cp.async staging, 2 CTAs/SM
// C = A*W + bias.  A: bf16 split [M][K] (lo at +M*K).
// WThi: bf16 split [N][K] (lo at +N*K).
// epi: 0 fp32 | 1 gelu->bf16split | 2 fp32+R | 3 fp16split | 4 fp16
// ============================================================
#define GTILE 10240
#define GEMM_SMEM (2 * 4 * GTILE)   // 81920

__global__ __launch_bounds__(256, 2) void gemm_bf16_kernel(
    const __nv_bfloat16* __restrict__ Ahi, const __nv_bfloat16* __restrict__ WThi,
    const float* __restrict__ bias, const float* __restrict__ R,
    float* __restrict__ C, int M, int N, int K, int epi)
{
    extern __shared__ char smem[];
    const int tid = threadIdx.x, wid = tid >> 5, lane = tid & 31;
    const int m0 = blockIdx.y * 128, n0 = blockIdx.x * 128;
    const int warpM = (wid & 3) * 32, warpN = (wid >> 2) * 64;
    const uint32_t sb = smem_u32(smem);

    const __nv_bfloat16* Alo  = Ahi  + (size_t)M * K;
    const __nv_bfloat16* WTlo = WThi + (size_t)N * K;
    const __nv_bfloat16* srcs[4] = {
        Ahi + (size_t)m0 * K,  Alo + (size_t)m0 * K,
        WThi + (size_t)n0 * K, WTlo + (size_t)n0 * K };

    float acc[2][8][4];
    #pragma unroll
    for (int i = 0; i < 2; i++)
        #pragma unroll
        for (int j = 0; j < 8; j++)
            #pragma unroll
            for (int q = 0; q < 4; q++) acc[i][j][q] = 0.0f;

    const int a_stat = (warpM + ((lane >> 3) & 1) * 8 + (lane & 7)) * 40 + (lane >> 4) * 8;
    const int b_stat = (warpN + ((lane >> 4) & 1) * 8 + (lane & 7)) * 40 + ((lane >> 3) & 1) * 8;
    const int NKB = K >> 5;

#define G_ISSUE(kb, buf) { \
    _Pragma("unroll") for (int i = 0; i < 8; i++) { \
        const int tile = i >> 1; \
        int r = ((tid >> 2) + 64 * i) & 127; \
        int s = tid & 3; \
        const __nv_bfloat16* src = srcs[tile] + (size_t)r * K + (kb) * 32 + s * 8; \
        uint32_t dst = sb + (buf) * 40960 + tile * GTILE + (uint32_t)(r * 40 + s * 8) * 2; \
        CP_ASYNC16(dst, src); \
    } \
    CP_COMMIT; }

#define G_COMPUTE(buf) { \
    uint32_t tb0 = sb + (buf) * 40960; \
    _Pragma("unroll") for (int ks = 0; ks < 2; ks++) { \
        const int Cc = ks * 16; \
        uint32_t fa[2][4], fl[2][4]; \
        _Pragma("unroll") for (int mb = 0; mb < 2; mb++) { \
            uint32_t ad = tb0 + (uint32_t)(a_stat + mb * 640 + Cc) * 2; \
            LDSM_X4(fa[mb][0], fa[mb][1], fa[mb][2], fa[mb][3], ad); \
            LDSM_X4(fl[mb][0], fl[mb][1], fl[mb][2], fl[mb][3], ad + GTILE); \
        } \
        _Pragma("unroll") for (int p = 0; p < 4; p++) { \
            uint32_t bh[4], bl[4]; \
            uint32_t bd = tb0 + 2 * GTILE + (uint32_t)(b_stat + p * 640 + Cc) * 2; \
            LDSM_X4(bh[0], bh[1], bh[2], bh[3], bd); \
            LDSM_X4(bl[0], bl[1], bl[2], bl[3], bd + GTILE); \
            _Pragma("unroll") for (int mb = 0; mb < 2; mb++) { \
                MMA_BF16(acc[mb][2*p],   fa[mb], bh[0], bh[1]); \
                MMA_BF16(acc[mb][2*p],   fa[mb], bl[0], bl[1]); \
                MMA_BF16(acc[mb][2*p],   fl[mb], bh[0], bh[1]); \
                MMA_BF16(acc[mb][2*p+1], fa[mb], bh[2], bh[3]); \
                MMA_BF16(acc[mb][2*p+1], fa[mb], bl[2], bl[3]); \
                MMA_BF16(acc[mb][2*p+1], fl[mb], bh[2], bh[3]); \
            } } } }

    G_ISSUE(0, 0);
    CP_WAIT0;
    __syncthreads();

    for (int kb = 0; kb < NKB; kb++) {
        if (kb + 1 < NKB) G_ISSUE(kb + 1, (kb + 1) & 1);
        G_COMPUTE(kb & 1);
        if (kb + 1 < NKB) {
            CP_WAIT0;
            __syncthreads();
        }
    }

    // epilogue
    const int g = lane >> 2, t = lane & 3;
    #pragma unroll
    for (int mb = 0; mb < 2; mb++)
        #pragma unroll
        for (int nb = 0; nb < 8; nb++) {
            int row = m0 + warpM + mb * 16 + g;
            int col = n0 + warpN + nb * 8 + 2 * t;
            float2 b2 = *(const float2*)(bias + col);
            float v0 = acc[mb][nb][0] + b2.x, v1 = acc[mb][nb][1] + b2.y;
            float v2 = acc[mb][nb][2] + b2.x, v3 = acc[mb][nb][3] + b2.y;
            size_t o0 = (size_t)row * N + col, o1 = (size_t)(row + 8) * N + col;
            if (epi == 0 || epi == 2) {
                if (epi == 2) {
                    float2 r0 = *(const float2*)(R + o0);
                    float2 r1 = *(const float2*)(R + o1);
                    v0 += r0.x; v1 += r0.y; v2 += r1.x; v3 += r1.y;
                }
                float2 c0 = {v0, v1}, c1 = {v2, v3};
                *(float2*)(C + o0) = c0;
                *(float2*)(C + o1) = c1;
            } else if (epi == 1) {
                v0 = gelu_exact(v0); v1 = gelu_exact(v1);
                v2 = gelu_exact(v2); v3 = gelu_exact(v3);
                __nv_bfloat16* Chi = (__nv_bfloat16*)C;
                __nv_bfloat16* Clo = Chi + (size_t)M * N;
                bfsplit_store(Chi + o0, Clo + o0, v0, v1);
                bfsplit_store(Chi + o1, Clo + o1, v2, v3);
            } else if (epi == 3) {
                __half* Chi = (__half*)C;
                __half* Clo = Chi + (size_t)M * N;
                hsplit_store(Chi + o0, Clo + o0, v0, v1);
                hsplit_store(Chi + o1, Clo + o1, v2, v3);
            } else {
                __half* Ch = (__half*)C;
                *(uint32_t*)(Ch + o0) = pack_h2(v0, v1);
                *(uint32_t*)(Ch + o1) = pack_h2(v2, v3);
            }
        }
}

// ============================================================
// flash attention, pre-split fp16 Q/K (x3), fp16 V
// double-buffered K/V smem with cp.async prefetch overlap
// 128 threads / 4 warps; BQ=64 (16 rows/warp); BK=64
// per-buffer: Khi[64][72] | Klo[64][72] | V[64][72]  (27648 B)
// ============================================================
#define FS 72
#define FK_LO 9216
#define FV    18432
#define FBUF  27648
#define FLASH_SMEM (2 * FBUF + 512)

__global__ __launch_bounds__(128) void flash_mma_kernel(
    const __half* __restrict__ Qhi, const __half* __restrict__ Khi,
    const __half* __restrict__ Vf, const int* __restrict__ ids,
    __nv_bfloat16* __restrict__ Ohi, int causal)
{
    extern __shared__ char fsm[];
    const uint32_t sb = smem_u32(fsm);
    float* nadd = (float*)(fsm + 2 * FBUF);

    const int tid = threadIdx.x, wid = tid >> 5, lane = tid & 31;
    const int qt = blockIdx.x, h = blockIdx.y, b = blockIdx.z;
    const int qbase = qt * 64;
    const int g = lane >> 2, t = lane & 3;

    const __half* Qlo = Qhi + (size_t)MTOK * DM;
    const __half* Klo = Khi + (size_t)MTOK * DM;
    __nv_bfloat16* Olo = Ohi + (size_t)MTOK * DM;

    const __half* Qph = Qhi + (size_t)b * SEQ * DM + h * DHEAD;
    const __half* Qpl = Qlo + (size_t)b * SEQ * DM + h * DHEAD;
    const __half* Kph = Khi + (size_t)b * SEQ * DM + h * DHEAD;
    const __half* Kpl = Klo + (size_t)b * SEQ * DM + h * DHEAD;
    const __half* Vp  = Vf  + (size_t)b * SEQ * DM + h * DHEAD;

#define F_STAGE(kbase, bufbase, nbuf) { \
    _Pragma("unroll") for (int i = 0; i < 8; i++) { \
        const int arr = i >> 2; \
        int r = (16 * i + (tid >> 3)) & 63; \
        int s = tid & 7; \
        const __half* src = (arr ? Kpl : Kph) + (size_t)((kbase) + r) * DM + s * 8; \
        uint32_t dst = sb + (bufbase) + arr * FK_LO + (uint32_t)(r * FS + s * 8) * 2; \
        CP_ASYNC16(dst, src); \
    } \
    _Pragma("unroll") for (int i = 0; i < 4; i++) { \
        int r = (16 * i + (tid >> 3)) & 63; \
        int s = tid & 7; \
        const __half* src = Vp + (size_t)((kbase) + r) * DM + s * 8; \
        uint32_t dst = sb + (bufbase) + FV + (uint32_t)(r * FS + s * 8) * 2; \
        CP_ASYNC16(dst, src); \
    } \
    if (tid < 64) \
        nadd[(nbuf) * 64 + tid] = (ids[b * SEQ + (kbase) + tid] == 0) ? NEGV : 0.0f; \
    CP_COMMIT; }

    // ---- stage Q into buf1 region, K/V tile 0 into buf0 ----
    #pragma unroll
    for (int i = 0; i < 8; i++) {
        const int arr = i >> 2;
        int r = (16 * i + (tid >> 3)) & 63;
        int s = tid & 7;
        const __half* src = (arr ? Qpl : Qph) + (size_t)(qbase + r) * DM + s * 8;
        uint32_t dst = sb + FBUF + arr * FK_LO + (uint32_t)(r * FS + s * 8) * 2;
        CP_ASYNC16(dst, src);
    }
    CP_COMMIT;
    F_STAGE(0, 0, 0);
    CP_WAIT0;
    __syncthreads();

    // ---- Q fragments from buf1 ----
    uint32_t qh[4][4], ql[4][4];
    {
        int arow = (lane & 15) + 16 * wid;
        int acb  = ((lane >> 4) & 1) * 8;
        #pragma unroll
        for (int kk = 0; kk < 4; kk++) {
            uint32_t ad = sb + FBUF + (uint32_t)(arow * FS + acb + kk * 16) * 2;
            LDSM_X4(qh[kk][0], qh[kk][1], qh[kk][2], qh[kk][3], ad);
            LDSM_X4(ql[kk][0], ql[kk][1], ql[kk][2], ql[kk][3], ad + FK_LO);
        }
    }

    float mA = -3.0e38f, mB = -3.0e38f, lA = 0.0f, lB = 0.0f;
    float O[8][4];
    #pragma unroll
    for (int nb = 0; nb < 8; nb++)
        #pragma unroll
        for (int q = 0; q < 4; q++) O[nb][q] = 0.0f;

    const int rowA = qbase + 16 * wid + g;
    const int nkt = causal ? (qt + 1) : (SEQ / 64);

    for (int kt = 0; kt < nkt; kt++) {
        const int cur = kt & 1;
        const uint32_t cb = sb + cur * FBUF;
        const bool diag = causal && (kt == qt);
        CP_WAIT0;            // prefetched tile landed (also: Q/K0 on first iter)
        __syncthreads();     // + all warps done with the buffer being refilled

        // ---- S = Q K^T (fp16x3) ----
        float sc[8][4];
        #pragma unroll
        for (int nb = 0; nb < 8; nb++)
            #pragma unroll
            for (int q = 0; q < 4; q++) sc[nb][q] = 0.0f;

        #pragma unroll
        for (int kk = 0; kk < 4; kk++) {
            #pragma unroll
            for (int p = 0; p < 4; p++) {
                int brow = p * 16 + ((lane >> 4) & 1) * 8 + (lane & 7);
                int bcol = kk * 16 + ((lane >> 3) & 1) * 8;
                uint32_t bd = cb + (uint32_t)(brow * FS + bcol) * 2;
                uint32_t bh[4], bl[4];
                LDSM_X4(bh[0], bh[1], bh[2], bh[3], bd);
                LDSM_X4(bl[0], bl[1], bl[2], bl[3], bd + FK_LO);
                MMA_F16(sc[2*p],   qh[kk], bh[0], bh[1]);
                MMA_F16(sc[2*p],   qh[kk], bl[0], bl[1]);
                MMA_F16(sc[2*p],   ql[kk], bh[0], bh[1]);
                MMA_F16(sc[2*p+1], qh[kk], bh[2], bh[3]);
                MMA_F16(sc[2*p+1], qh[kk], bl[2], bl[3]);
                MMA_F16(sc[2*p+1], ql[kk], bh[2], bh[3]);
            }
        }

        // ---- prefetch next tile (overlaps softmax + PV) ----
        if (kt + 1 < nkt)
            F_STAGE((kt + 1) * 64, (1 - cur) * FBUF, 1 - cur);

        // ---- scale + masks + online softmax ----
        const int kbase = kt * 64;
        float rmaxA = -3.0e38f, rmaxB = -3.0e38f;
        #pragma unroll
        for (int nb = 0; nb < 8; nb++) {
            int col0 = kbase + nb * 8 + 2 * t;
            float p0 = nadd[cur * 64 + nb * 8 + 2 * t];
            float p1 = nadd[cur * 64 + nb * 8 + 2 * t + 1];
            float v0 = sc[nb][0] * 0.125f + p0;
            float v1 = sc[nb][1] * 0.125f + p1;
            float v2 = sc[nb][2] * 0.125f + p0;
            float v3 = sc[nb][3] * 0.125f + p1;
            if (diag) {
                if (col0     > rowA)     v0 += NEGV;
                if (col0 + 1 > rowA)     v1 += NEGV;
                if (col0     > rowA + 8) v2 += NEGV;
                if (col0 + 1 > rowA + 8) v3 += NEGV;
            }
            sc[nb][0] = v0; sc[nb][1] = v1; sc[nb][2] = v2; sc[nb][3] = v3;
            rmaxA = fmaxf(rmaxA, fmaxf(v0, v1));
            rmaxB = fmaxf(rmaxB, fmaxf(v2, v3));
        }
        #pragma unroll
        for (int o = 1; o <= 2; o <<= 1) {
            rmaxA = fmaxf(rmaxA, __shfl_xor_sync(0xffffffffu, rmaxA, o));
            rmaxB = fmaxf(rmaxB, __shfl_xor_sync(0xffffffffu, rmaxB, o));
        }
        float mnA = fmaxf(mA, rmaxA), mnB = fmaxf(mB, rmaxB);
        float aA = __expf(mA - mnA), aB = __expf(mB - mnB);
        mA = mnA; mB = mnB;

        uint32_t af[4][4];
        float sA = 0.0f, sB = 0.0f;
        #pragma unroll
        for (int nb = 0; nb < 8; nb++) {
            float p0 = __expf(sc[nb][0] - mnA);
            float p1 = __expf(sc[nb][1] - mnA);
            float p2 = __expf(sc[nb][2] - mnB);
            float p3 = __expf(sc[nb][3] - mnB);
            __half h0 = __float2half(p0), h1 = __float2half(p1);
            __half h2 = __float2half(p2), h3 = __float2half(p3);
            sA += __half2float(h0) + __half2float(h1);
            sB += __half2float(h2) + __half2float(h3);
            __half2 u01; u01.x = h0; u01.y = h1;
            __half2 u23; u23.x = h2; u23.y = h3;
            int kk = nb >> 1, hi = nb & 1;
            af[kk][hi * 2 + 0] = *(uint32_t*)&u01;
            af[kk][hi * 2 + 1] = *(uint32_t*)&u23;
        }
        #pragma unroll
        for (int o = 1; o <= 2; o <<= 1) {
            sA += __shfl_xor_sync(0xffffffffu, sA, o);
            sB += __shfl_xor_sync(0xffffffffu, sB, o);
        }
        lA = lA * aA + sA; lB = lB * aB + sB;
        #pragma unroll
        for (int nb = 0; nb < 8; nb++) {
            O[nb][0] *= aA; O[nb][1] *= aA;
            O[nb][2] *= aB; O[nb][3] *= aB;
        }

        // ---- O += P V (ldmatrix.trans on row-major V) ----
        #pragma unroll
        for (int kk = 0; kk < 4; kk++) {
            #pragma unroll
            for (int nbp = 0; nbp < 4; nbp++) {
                int vrow = kk * 16 + (lane & 15);
                int vcol = nbp * 16 + (lane >> 4) * 8;
                uint32_t bd = cb + FV + (uint32_t)(vrow * FS + vcol) * 2;
                uint32_t v0, v1, v2, v3;
                LDSM_X4_T(v0, v1, v2, v3, bd);
                MMA_F16(O[2*nbp],     af[kk], v0, v1);
                MMA_F16(O[2*nbp + 1], af[kk], v2, v3);
            }
        }
    }

    // ---- write out (bf16 split for next GEMM's A) ----
    float iA = 1.0f / lA, iB = 1.0f / lB;
    #pragma unroll
    for (int nb = 0; nb < 8; nb++) {
        int col = h * DHEAD + nb * 8 + 2 * t;
        size_t off0 = ((size_t)b * SEQ + rowA) * DM + col;
        size_t off1 = ((size_t)b * SEQ + rowA + 8) * DM + col;
        bfsplit_store(Ohi + off0, Olo + off0, O[nb][0] * iA, O[nb][1] * iA);
        bfsplit_store(Ohi + off1, Olo + off1, O[nb][2] * iB, O[nb][3] * iB);
    }
}

// ============================================================
// host pipeline
// ============================================================
extern "C" void kernel_launch(void* const* d_in, const int* in_sizes, int n_in,
                              void* d_out, int out_size)
{
    const float* input_embedding = (const float*)d_in[0];
    const int*   input_ids       = (const int*)  d_in[1];
    const int*   target_ids      = (const int*)  d_in[2];
    const float* tok_emb = (const float*)d_in[3];
    const float* pos_emb = (const float*)d_in[4];
    const float* ln1_g = (const float*)d_in[5],  *ln1_b = (const float*)d_in[6];
    const float* q1_w  = (const float*)d_in[7],  *q1_b  = (const float*)d_in[8];
    const float* k1_w  = (const float*)d_in[9],  *k1_b  = (const float*)d_in[10];
    const float* v1_w  = (const float*)d_in[11], *v1_b  = (const float*)d_in[12];
    const float* out1_w= (const float*)d_in[13], *out1_b= (const float*)d_in[14];
    const float* ln2_g = (const float*)d_in[15], *ln2_b = (const float*)d_in[16];
    const float* q2_w  = (const float*)d_in[17], *q2_b  = (const float*)d_in[18];
    const float* k2_w  = (const float*)d_in[19], *k2_b  = (const float*)d_in[20];
    const float* v2_w  = (const float*)d_in[21], *v2_b  = (const float*)d_in[22];
    const float* out2_w= (const float*)d_in[23], *out2_b= (const float*)d_in[24];
    const float* ln3_g = (const float*)d_in[25], *ln3_b = (const float*)d_in[26];
    const float* mlp_w1= (const float*)d_in[27], *mlp_b1= (const float*)d_in[28];
    const float* mlp_w2= (const float*)d_in[29], *mlp_b2= (const float*)d_in[30];

    float *xln, *xs, *ies, *qb, *kb, *vb, *ab, *hb, *rb, *zb, *zs, *tb, *wt;
    cudaGetSymbolAddress((void**)&xln, g_xln);
    cudaGetSymbolAddress((void**)&xs,  g_xs);
    cudaGetSymbolAddress((void**)&ies, g_ies);
    cudaGetSymbolAddress((void**)&qb,  g_qb);
    cudaGetSymbolAddress((void**)&kb,  g_kb);
    cudaGetSymbolAddress((void**)&vb,  g_vb);
    cudaGetSymbolAddress((void**)&ab,  g_ab);
    cudaGetSymbolAddress((void**)&hb,  g_hb);
    cudaGetSymbolAddress((void**)&rb,  g_rb);
    cudaGetSymbolAddress((void**)&zb,  g_zb);
    cudaGetSymbolAddress((void**)&zs,  g_zs);
    cudaGetSymbolAddress((void**)&tb,  g_tb);
    cudaGetSymbolAddress((void**)&wt,  g_wt);

    cudaFuncSetAttribute(gemm_bf16_kernel,
                         cudaFuncAttributeMaxDynamicSharedMemorySize, GEMM_SMEM);
    cudaFuncSetAttribute(flash_mma_kernel,
                         cudaFuncAttributeMaxDynamicSharedMemorySize, FLASH_SMEM);

    // ---- one-time prep: weight transpose+split, input_embedding split ----
    {
        dim3 g1(DM / 32, DM / 32);
        transpose_split_kernel<<<g1, 256>>>(q1_w,  (__nv_bfloat16*)(wt + WT_Q1), DM, DM);
        transpose_split_kernel<<<g1, 256>>>(k1_w,  (__nv_bfloat16*)(wt + WT_K1), DM, DM);
        transpose_split_kernel<<<g1, 256>>>(v1_w,  (__nv_bfloat16*)(wt + WT_V1), DM, DM);
        transpose_split_kernel<<<g1, 256>>>(out1_w,(__nv_bfloat16*)(wt + WT_O1), DM, DM);
        transpose_split_kernel<<<g1, 256>>>(q2_w,  (__nv_bfloat16*)(wt + WT_Q2), DM, DM);
        transpose_split_kernel<<<g1, 256>>>(k2_w,  (__nv_bfloat16*)(wt + WT_K2), DM, DM);
        transpose_split_kernel<<<g1, 256>>>(v2_w,  (__nv_bfloat16*)(wt + WT_V2), DM, DM);
        transpose_split_kernel<<<g1, 256>>>(out2_w,(__nv_bfloat16*)(wt + WT_O2), DM, DM);
        dim3 gm1(4 * DM / 32, DM / 32);
        transpose_split_kernel<<<gm1, 256>>>(mlp_w1, (__nv_bfloat16*)(wt + WT_M1), DM, 4 * DM);
        dim3 gm2(DM / 32, 4 * DM / 32);
        transpose_split_kernel<<<gm2, 256>>>(mlp_w2, (__nv_bfloat16*)(wt + WT_M2), 4 * DM, DM);
        split_bf16_kernel<<<MTOK * DM / 1024, 256>>>(input_embedding,
                                                     (__nv_bfloat16*)ies, MTOK * DM);
    }

    dim3 gN1(DM / 128, MTOK / 128);          // (8, 32)
    dim3 gN4(4 * DM / 128, MTOK / 128);      // (32, 32)
    dim3 gF(SEQ / 64, NH, BATCH);

    // x = LN1(tok_emb[tgt] + pos)  -> xln (fp32) + xs (bf16 split)
    embed_ln_kernel<<<MTOK, 256>>>(target_ids, tok_emb, pos_emb, ln1_g, ln1_b,
                                   xln, (__nv_bfloat16*)xs);

    // self-attention
    gemm_bf16_kernel<<<gN1, 256, GEMM_SMEM>>>((const __nv_bfloat16*)xs,
        (const __nv_bfloat16*)(wt + WT_Q1), q1_b, nullptr, qb, MTOK, DM, DM, 3);
    gemm_bf16_kernel<<<gN1, 256, GEMM_SMEM>>>((const __nv_bfloat16*)xs,
        (const __nv_bfloat16*)(wt + WT_K1), k1_b, nullptr, kb, MTOK, DM, DM, 3);
    gemm_bf16_kernel<<<gN1, 256, GEMM_SMEM>>>((const __nv_bfloat16*)xs,
        (const __nv_bfloat16*)(wt + WT_V1), v1_b, nullptr, vb, MTOK, DM, DM, 4);
    flash_mma_kernel<<<gF, 128, FLASH_SMEM>>>((const __half*)qb, (const __half*)kb,
        (const __half*)vb, target_ids, (__nv_bfloat16*)ab, 1);
    gemm_bf16_kernel<<<gN1, 256, GEMM_SMEM>>>((const __nv_bfloat16*)ab,
        (const __nv_bfloat16*)(wt + WT_O1), out1_b, xln, hb, MTOK, DM, DM, 2);

    // cross-attention (residual uses LN2 output, matching reference)
    ln_kernel<<<MTOK, 256>>>(hb, ln2_g, ln2_b, zb, (__nv_bfloat16*)zs);
    gemm_bf16_kernel<<<gN1, 256, GEMM_SMEM>>>((const __nv_bfloat16*)zs,
        (const __nv_bfloat16*)(wt + WT_Q2), q2_b, nullptr, qb, MTOK, DM, DM, 3);
    gemm_bf16_kernel<<<gN1, 256, GEMM_SMEM>>>((const __nv_bfloat16*)ies,
        (const __nv_bfloat16*)(wt + WT_K2), k2_b, nullptr, kb, MTOK, DM, DM, 3);
    gemm_bf16_kernel<<<gN1, 256, GEMM_SMEM>>>((const __nv_bfloat16*)ies,
        (const __nv_bfloat16*)(wt + WT_V2), v2_b, nullptr, vb, MTOK, DM, DM, 4);
    flash_mma_kernel<<<gF, 128, FLASH_SMEM>>>((const __half*)qb, (const __half*)kb,
        (const __half*)vb, input_ids, (__nv_bfloat16*)ab, 0);
    gemm_bf16_kernel<<<gN1, 256, GEMM_SMEM>>>((const __nv_bfloat16*)ab,
        (const __nv_bfloat16*)(wt + WT_O2), out2_b, zb, rb, MTOK, DM, DM, 2);

    // MLP
    ln_kernel<<<MTOK, 256>>>(rb, ln3_g, ln3_b, zb, (__nv_bfloat16*)zs);
    gemm_bf16_kernel<<<gN4, 256, GEMM_SMEM>>>((const __nv_bfloat16*)zs,
        (const __nv_bfloat16*)(wt + WT_M1), mlp_b1, nullptr, tb, MTOK, 4 * DM, DM, 1);
    gemm_bf16_kernel<<<gN1, 256, GEMM_SMEM>>>((const __nv_bfloat16*)tb,
        (const __nv_bfloat16*)(wt + WT_M2), mlp_b2, rb, (float*)d_out, MTOK, DM, 4 * DM, 2);
}